// round 10
// baseline (speedup 1.0000x reference)
#include <cuda_runtime.h>
#include <cuda_fp16.h>
#include <math.h>

#define NPTS 4096
#define DIMS 64
#define MAX_ITERS 44
#define NB 256                       /* persistent grid; occupancy-2 guaranteed */
#define NEGLOGN (-8.317766166719343f)
#define LN2f 0.6931471805599453f
#define INVLN2f 1.4426950408889634f
#define C0Z (NEGLOGN * INVLN2f)

// ---------------- static device scratch ----------------
__device__ float dCxy[(size_t)NPTS * NPTS];
__device__ float dCxx[(size_t)NPTS * NPTS];
__device__ float dCyy[(size_t)NPTS * NPTS];
__device__ __align__(16) __half hCxy[(size_t)NPTS * NPTS];
__device__ __align__(16) __half hCxx[(size_t)NPTS * NPTS];
__device__ __align__(16) __half hCyy[(size_t)NPTS * NPTS];
__device__ float dRmin[4][NPTS];      // [0] Cxy rows, [2] Cxx, [3] Cyy
__device__ float dX2[NPTS];
__device__ float dY2[NPTS];
__device__ float dMinP[128 * DIMS];
__device__ float dMaxP[128 * DIMS];
__device__ float dEps[MAX_ITERS];
__device__ int   dNeps;
// slots: 0=f_ba, 1=g_ab, 2=f_aa, 3=g_bb
__device__ float dF[2][4][NPTS];
__device__ float dFin[4][NPTS];
__device__ __align__(16) float2 dColPart[128][NPTS];   // [band][col]
__device__ unsigned int dBarCnt;
__device__ volatile unsigned int dBarGen;

// ---------------- helpers ----------------
__device__ __forceinline__ float ex2f_(float x) {
    float r; asm("ex2.approx.ftz.f32 %0, %1;" : "=f"(r) : "f"(x)); return r;
}
__device__ __forceinline__ float lg2f_(float x) {
    float r; asm("lg2.approx.ftz.f32 %0, %1;" : "=f"(r) : "f"(x)); return r;
}
__device__ __forceinline__ void atomicMinFloat(float* addr, float v) {
    int* ai = (int*)addr;
    int old = *ai;
    while (__int_as_float(old) > v) {
        int assumed = old;
        old = atomicCAS(ai, assumed, __float_as_int(v));
        if (old == assumed) break;
    }
}
__device__ __forceinline__ void atomicMaxFloat(float* addr, float v) {
    int* ai = (int*)addr;
    int old = *ai;
    while (__int_as_float(old) < v) {
        int assumed = old;
        old = atomicCAS(ai, assumed, __float_as_int(v));
        if (old == assumed) break;
    }
}
__device__ __forceinline__ void lse_comb(float2& a, float mo, float so) {
    float mn = fmaxf(a.x, mo);
    a.y = a.y * ex2f_(a.x - mn) + so * ex2f_(mo - mn);
    a.x = mn;
}

// ---------------- 1) prep ----------------
__global__ void __launch_bounds__(256) prep_k(const float* __restrict__ x,
                                              const float* __restrict__ y) {
    int t = threadIdx.x, b = blockIdx.x;  // 128 x 256
    int gi = b * 256 + t;
    if (gi < 4 * NPTS) ((float*)dRmin)[gi] = INFINITY;

    int dim = t & 63, sub = t >> 6;
    float mn = INFINITY, mx = -INFINITY;
    for (int row = b * 4 + sub; row < 2 * NPTS; row += 128 * 4) {
        const float* p = (row < NPTS) ? (x + (size_t)row * DIMS)
                                      : (y + (size_t)(row - NPTS) * DIMS);
        float v = p[dim];
        mn = fminf(mn, v); mx = fmaxf(mx, v);
    }
    __shared__ float smn[256], smx[256];
    smn[t] = mn; smx[t] = mx;
    __syncthreads();
    if (t < 64) {
        mn = fminf(fminf(smn[t], smn[t + 64]), fminf(smn[t + 128], smn[t + 192]));
        mx = fmaxf(fmaxf(smx[t], smx[t + 64]), fmaxf(smx[t + 128], smx[t + 192]));
        dMinP[b * 64 + t] = mn;
        dMaxP[b * 64 + t] = mx;
    }

    int row = b * 64 + (t >> 2), q = t & 3;
    const float* p = (row < NPTS) ? (x + (size_t)row * DIMS)
                                  : (y + (size_t)(row - NPTS) * DIMS);
    float s = 0.f;
#pragma unroll
    for (int k = 0; k < 4; k++) {
        float4 v = ((const float4*)p)[q * 4 + k];
        s += v.x * v.x + v.y * v.y + v.z * v.z + v.w * v.w;
    }
    s += __shfl_xor_sync(0xffffffffu, s, 1);
    s += __shfl_xor_sync(0xffffffffu, s, 2);
    if (q == 0) {
        if (row < NPTS) dX2[row] = s; else dY2[row - NPTS] = s;
    }
}

// ---------------- 2) schedule ----------------
__global__ void sched_k() {
    int t = threadIdx.x;  // 64
    __shared__ float sr2[64];
    __shared__ float sdiam;
    float mn = INFINITY, mx = -INFINITY;
    for (int b = 0; b < 128; b++) {
        mn = fminf(mn, dMinP[b * 64 + t]);
        mx = fmaxf(mx, dMaxP[b * 64 + t]);
    }
    float r = mx - mn;
    sr2[t] = r * r;
    __syncthreads();
    if (t == 0) {
        float d2 = 0.f;
        for (int d = 0; d < 64; d++) d2 += sr2[d];
        sdiam = sqrtf(d2);
    }
    __syncthreads();
    float diam = sdiam;
    double start = 2.0 * log((double)diam);
    double stop  = 2.0 * log(0.05);
    double step  = 2.0 * log(0.8);
    double cnt = ceil((stop - start) / step);
    int n_ar = (cnt > 0.0) ? (int)cnt : 0;
    if (n_ar > MAX_ITERS - 2) n_ar = MAX_ITERS - 2;
    if (t == 0) { dEps[0] = diam * diam; dNeps = n_ar + 2; dBarCnt = 0; }
    if (t >= 1 && t < MAX_ITERS) {
        int k = t - 1;
        dEps[t] = (k < n_ar) ? (float)exp(start + (double)k * step) : 0.0025f;
    }
}

// ---------------- 3) cost matrices + row mins ----------------
__global__ void __launch_bounds__(256) gemm_cost(const float* __restrict__ x,
                                                 const float* __restrict__ y) {
    int seg  = blockIdx.x >> 10;
    int tile = blockIdx.x & 1023;
    int bm = tile >> 5, bn = tile & 31;
    const float *A, *B, *a2, *b2;
    float* Cc;
    int slot;
    if (seg == 0)      { A = x; B = y; a2 = dX2; b2 = dY2; Cc = dCxy; slot = 0; }
    else if (seg == 1) { A = x; B = x; a2 = dX2; b2 = dX2; Cc = dCxx; slot = 2; }
    else               { A = y; B = y; a2 = dY2; b2 = dY2; Cc = dCyy; slot = 3; }

    __shared__ float As[32][128];
    __shared__ float Bs[32][128];
    __shared__ float redR[128][16];
    int t = threadIdx.x;
    int m0 = bm * 128, n0 = bn * 128;
    int tm = t >> 4, tn = t & 15;

    float acc[8][8];
#pragma unroll
    for (int i = 0; i < 8; i++)
#pragma unroll
        for (int j = 0; j < 8; j++) acc[i][j] = 0.f;

    for (int kc = 0; kc < 2; kc++) {
#pragma unroll
        for (int l = 0; l < 4; l++) {
            int lin = t + l * 256;
            int r  = lin >> 3;
            int kq = (lin & 7) << 2;
            float4 va = *(const float4*)(A + (size_t)(m0 + r) * DIMS + kc * 32 + kq);
            As[kq + 0][r] = va.x; As[kq + 1][r] = va.y;
            As[kq + 2][r] = va.z; As[kq + 3][r] = va.w;
            float4 vb = *(const float4*)(B + (size_t)(n0 + r) * DIMS + kc * 32 + kq);
            Bs[kq + 0][r] = vb.x; Bs[kq + 1][r] = vb.y;
            Bs[kq + 2][r] = vb.z; Bs[kq + 3][r] = vb.w;
        }
        __syncthreads();
#pragma unroll 8
        for (int k = 0; k < 32; k++) {
            float ar[8], br[8];
#pragma unroll
            for (int i = 0; i < 4; i++) {
                ar[i]     = As[k][tm * 4 + i];
                ar[4 + i] = As[k][64 + tm * 4 + i];
                br[i]     = Bs[k][tn * 4 + i];
                br[4 + i] = Bs[k][64 + tn * 4 + i];
            }
#pragma unroll
            for (int i = 0; i < 8; i++)
#pragma unroll
                for (int j = 0; j < 8; j++) acc[i][j] += ar[i] * br[j];
        }
        __syncthreads();
    }

    float b2r[8];
#pragma unroll
    for (int j = 0; j < 4; j++) {
        b2r[j]     = b2[n0 + tn * 4 + j];
        b2r[4 + j] = b2[n0 + 64 + tn * 4 + j];
    }
#pragma unroll
    for (int i = 0; i < 8; i++) {
        int rl = (i < 4) ? (tm * 4 + i) : (64 + tm * 4 + (i - 4));
        int row = m0 + rl;
        float ha = 0.5f * a2[row];
        float4 v0, v1;
        v0.x = ha + 0.5f * b2r[0] - acc[i][0];
        v0.y = ha + 0.5f * b2r[1] - acc[i][1];
        v0.z = ha + 0.5f * b2r[2] - acc[i][2];
        v0.w = ha + 0.5f * b2r[3] - acc[i][3];
        v1.x = ha + 0.5f * b2r[4] - acc[i][4];
        v1.y = ha + 0.5f * b2r[5] - acc[i][5];
        v1.z = ha + 0.5f * b2r[6] - acc[i][6];
        v1.w = ha + 0.5f * b2r[7] - acc[i][7];
        *(float4*)(Cc + (size_t)row * NPTS + n0 + tn * 4)      = v0;
        *(float4*)(Cc + (size_t)row * NPTS + n0 + 64 + tn * 4) = v1;
        float rm = fminf(fminf(fminf(v0.x, v0.y), fminf(v0.z, v0.w)),
                         fminf(fminf(v1.x, v1.y), fminf(v1.z, v1.w)));
        redR[rl][tn] = rm;
    }
    __syncthreads();
    if (t < 128) {
        float r = INFINITY;
#pragma unroll
        for (int k = 0; k < 16; k++) r = fminf(r, redR[t][k]);
        atomicMinFloat(&dRmin[slot][m0 + t], r);
    }
}

// ---------------- 4) fp32 -> fp16 (row-min relative) ----------------
__global__ void __launch_bounds__(256) conv_k() {
    int seg3  = blockIdx.x >> 13;
    int local = blockIdx.x & 8191;
    const float* C = (seg3 == 0) ? dCxy : (seg3 == 1) ? dCxx : dCyy;
    __half* H = (seg3 == 0) ? hCxy : (seg3 == 1) ? hCxx : hCyy;
    const float* rmin = (seg3 == 0) ? dRmin[0] : (seg3 == 1) ? dRmin[2] : dRmin[3];
    size_t idx = (size_t)local * 2048 + threadIdx.x * 8;
    int row = (int)(idx >> 12);
    float rm = rmin[row];
    float4 a = *(const float4*)(C + idx);
    float4 b = *(const float4*)(C + idx + 4);
    half2 q0 = __floats2half2_rn(a.x - rm, a.y - rm);
    half2 q1 = __floats2half2_rn(a.z - rm, a.w - rm);
    half2 q2 = __floats2half2_rn(b.x - rm, b.y - rm);
    half2 q3 = __floats2half2_rn(b.z - rm, b.w - rm);
    uint4 o;
    o.x = *(unsigned*)&q0; o.y = *(unsigned*)&q1;
    o.z = *(unsigned*)&q2; o.w = *(unsigned*)&q3;
    *(uint4*)(H + idx) = o;
}

// ---------------- grid barrier ----------------
__device__ __forceinline__ void grid_barrier() {
    __syncthreads();
    if (threadIdx.x == 0) {
        unsigned gen = dBarGen;
        __threadfence();
        if (atomicAdd(&dBarCnt, 1) == NB - 1) {
            dBarCnt = 0;
            __threadfence();
            dBarGen = gen + 1;
        } else {
            while (dBarGen == gen) __nanosleep(64);
        }
        __threadfence();
    }
    __syncthreads();
}

// ---------------- row softmin: 2 rows/warp, exp2 domain, skip ----------------
__device__ __forceinline__ void lse_pair(const __half* __restrict__ Mrow0,
                                         const float* __restrict__ Hs,
                                         float negs1,
                                         float& M0o, float& S0o, float& M1o, float& S1o) {
    const unsigned FULL = 0xffffffffu;
    int lane = threadIdx.x & 31;
    const uint4* p0 = (const uint4*)Mrow0 + lane;
    const uint4* p1 = (const uint4*)(Mrow0 + NPTS) + lane;
    float m0 = -INFINITY, s0 = 0.f, m1 = -INFINITY, s1 = 0.f;
    uint4 A0 = __ldg(p0);
    uint4 A1 = __ldg(p1);
    int hIdx = lane * 8;
#pragma unroll 4
    for (int c = 0; c < 16; c++) {
        uint4 a0 = A0, a1 = A1;
        if (c < 15) { p0 += 32; p1 += 32; A0 = __ldg(p0); A1 = __ldg(p1); }
        float h[8];
        float4 hA = *(const float4*)&Hs[hIdx];
        float4 hB = *(const float4*)&Hs[hIdx + 4];
        h[0] = hA.x; h[1] = hA.y; h[2] = hA.z; h[3] = hA.w;
        h[4] = hB.x; h[5] = hB.y; h[6] = hB.z; h[7] = hB.w;
        hIdx += 256;
        float z0[8], z1[8];
        const half2* q0 = (const half2*)&a0;
        const half2* q1 = (const half2*)&a1;
#pragma unroll
        for (int k = 0; k < 4; k++) {
            float2 f0 = __half22float2(q0[k]);
            float2 f1 = __half22float2(q1[k]);
            z0[2 * k]     = fmaf(f0.x, negs1, h[2 * k]);
            z0[2 * k + 1] = fmaf(f0.y, negs1, h[2 * k + 1]);
            z1[2 * k]     = fmaf(f1.x, negs1, h[2 * k]);
            z1[2 * k + 1] = fmaf(f1.y, negs1, h[2 * k + 1]);
        }
        float c0m = fmaxf(fmaxf(fmaxf(z0[0], z0[1]), fmaxf(z0[2], z0[3])),
                          fmaxf(fmaxf(z0[4], z0[5]), fmaxf(z0[6], z0[7])));
        float c1m = fmaxf(fmaxf(fmaxf(z1[0], z1[1]), fmaxf(z1[2], z1[3])),
                          fmaxf(fmaxf(z1[4], z1[5]), fmaxf(z1[6], z1[7])));
        if (!__all_sync(FULL, (c0m - m0) < -64.f)) {
            if (c0m > m0) { s0 *= ex2f_(m0 - c0m); m0 = c0m; }
            float e0 = ex2f_(z0[0] - m0), e1 = ex2f_(z0[1] - m0);
            float e2 = ex2f_(z0[2] - m0), e3 = ex2f_(z0[3] - m0);
            float e4 = ex2f_(z0[4] - m0), e5 = ex2f_(z0[5] - m0);
            float e6 = ex2f_(z0[6] - m0), e7 = ex2f_(z0[7] - m0);
            s0 += ((e0 + e1) + (e2 + e3)) + ((e4 + e5) + (e6 + e7));
        }
        if (!__all_sync(FULL, (c1m - m1) < -64.f)) {
            if (c1m > m1) { s1 *= ex2f_(m1 - c1m); m1 = c1m; }
            float e0 = ex2f_(z1[0] - m1), e1 = ex2f_(z1[1] - m1);
            float e2 = ex2f_(z1[2] - m1), e3 = ex2f_(z1[3] - m1);
            float e4 = ex2f_(z1[4] - m1), e5 = ex2f_(z1[5] - m1);
            float e6 = ex2f_(z1[6] - m1), e7 = ex2f_(z1[7] - m1);
            s1 += ((e0 + e1) + (e2 + e3)) + ((e4 + e5) + (e6 + e7));
        }
        if ((c & 3) == 3) {
            float w = m0;
#pragma unroll
            for (int o = 16; o; o >>= 1) w = fmaxf(w, __shfl_xor_sync(FULL, w, o));
            if (w > m0) { s0 *= ex2f_(m0 - w); m0 = w; }
            w = m1;
#pragma unroll
            for (int o = 16; o; o >>= 1) w = fmaxf(w, __shfl_xor_sync(FULL, w, o));
            if (w > m1) { s1 *= ex2f_(m1 - w); m1 = w; }
        }
    }
#pragma unroll
    for (int o = 16; o; o >>= 1) {
        s0 += __shfl_xor_sync(FULL, s0, o);
        s1 += __shfl_xor_sync(FULL, s1, o);
    }
    M0o = m0; S0o = s0; M1o = m1; S1o = s1;
}

// ---------------- 5) persistent Sinkhorn (fused xy row+col) ----------------
// blocks: 0-127 xy (32-row bands), 128-191 xx (64 rows), 192-255 yy (64 rows)
__global__ void __launch_bounds__(256, 2) sinkhorn_k(float* __restrict__ out) {
    int bid = blockIdx.x;
    int t = threadIdx.x, w = t >> 5, lane = t & 31;
    __shared__ __align__(16) float Hs[NPTS];
    __shared__ float HcolS[32];
    __shared__ float2 comb[8][8];

    int segKind, r0, nrp, rowslot, hslot;
    const __half* Mbase;
    const float* rmin;
    if (bid < 128)      { segKind = 0; r0 = bid * 32; nrp = 2; rowslot = 0; hslot = 1;
                          Mbase = hCxy; rmin = dRmin[0]; }
    else if (bid < 192) { segKind = 1; r0 = (bid - 128) * 64; nrp = 4; rowslot = 2; hslot = 2;
                          Mbase = hCxx; rmin = dRmin[2]; }
    else                { segKind = 2; r0 = (bid - 192) * 64; nrp = 4; rowslot = 3; hslot = 3;
                          Mbase = hCyy; rmin = dRmin[3]; }

    int n = dNeps;
    for (int pass = 0; pass <= n + 1; pass++) {
        float eps = (pass == 0) ? dEps[0] : ((pass <= n) ? dEps[pass - 1] : 0.0025f);
        float s1f = (1.f / eps) * INVLN2f;
        float el2 = eps * LN2f;
        int rd = pass & 1;
        bool avg = (pass >= 1 && pass <= n);
        bool fin = (pass == n + 1);

        // fill Hs (row-direction H)
        if (pass == 0) {
            for (int i = t * 4; i < NPTS; i += 1024) {
                float4 o; o.x = C0Z; o.y = C0Z; o.z = C0Z; o.w = C0Z;
                *(float4*)&Hs[i] = o;
            }
        } else {
            const float4* Hv = (const float4*)dF[rd][hslot];
            for (int i = t; i < NPTS / 4; i += 256) {
                float4 hv = __ldcg(&Hv[i]);
                float4 o;
                o.x = fmaf(hv.x, s1f, C0Z); o.y = fmaf(hv.y, s1f, C0Z);
                o.z = fmaf(hv.z, s1f, C0Z); o.w = fmaf(hv.w, s1f, C0Z);
                *(float4*)&Hs[i * 4] = o;
            }
        }
        // col-direction H (xy only)
        if (segKind == 0 && t < 32) {
            float fp = (pass == 0) ? 0.f : __ldcg(&dF[rd][0][r0 + t]);
            HcolS[t] = fmaf(fp - rmin[r0 + t], s1f, C0Z);
        }
        __syncthreads();

        // ---- row phase ----
        for (int rp = 0; rp < nrp; rp++) {
            int row0 = r0 + rp * 16 + w * 2;
            float m0, s0, m1, s1;
            lse_pair(Mbase + (size_t)row0 * NPTS, Hs, -s1f, m0, s0, m1, s1);
            if (lane == 0) {
                float ft0 = rmin[row0]     - el2 * (m0 + lg2f_(s0));
                float ft1 = rmin[row0 + 1] - el2 * (m1 + lg2f_(s1));
                if (fin) {
                    dFin[rowslot][row0]     = ft0;
                    dFin[rowslot][row0 + 1] = ft1;
                } else {
                    float* dstp = dF[rd ^ 1][rowslot];
                    if (avg) {
                        ft0 = 0.5f * (__ldcg(&dF[rd][rowslot][row0]) + ft0);
                        ft1 = 0.5f * (__ldcg(&dF[rd][rowslot][row0 + 1]) + ft1);
                    }
                    dstp[row0] = ft0;
                    dstp[row0 + 1] = ft1;
                }
            }
        }

        // ---- col phase (xy blocks): 16 cols/thread over 32 rows ----
        if (segKind == 0) {
            float mC[16], sC[16];
#pragma unroll
            for (int k = 0; k < 16; k++) { mC[k] = -INFINITY; sC[k] = 0.f; }
            const uint4* cp = (const uint4*)(Mbase + (size_t)r0 * NPTS + t * 16);
            for (int r = 0; r < 32; r++) {
                uint4 a = __ldg(cp);
                uint4 b = __ldg(cp + 1);
                cp += NPTS / 8;
                float Hc = HcolS[r];
                const half2* qa = (const half2*)&a;
                const half2* qb = (const half2*)&b;
#pragma unroll
                for (int k = 0; k < 4; k++) {
                    float2 fa = __half22float2(qa[k]);
                    float2 fb = __half22float2(qb[k]);
                    float za0 = fmaf(fa.x, -s1f, Hc), za1 = fmaf(fa.y, -s1f, Hc);
                    float zb0 = fmaf(fb.x, -s1f, Hc), zb1 = fmaf(fb.y, -s1f, Hc);
                    int i0 = 2 * k, i1 = 2 * k + 1, i2 = 8 + 2 * k, i3 = 8 + 2 * k + 1;
                    if (za0 > mC[i0]) { sC[i0] = sC[i0] * ex2f_(mC[i0] - za0) + 1.f; mC[i0] = za0; }
                    else sC[i0] += ex2f_(za0 - mC[i0]);
                    if (za1 > mC[i1]) { sC[i1] = sC[i1] * ex2f_(mC[i1] - za1) + 1.f; mC[i1] = za1; }
                    else sC[i1] += ex2f_(za1 - mC[i1]);
                    if (zb0 > mC[i2]) { sC[i2] = sC[i2] * ex2f_(mC[i2] - zb0) + 1.f; mC[i2] = zb0; }
                    else sC[i2] += ex2f_(zb0 - mC[i2]);
                    if (zb1 > mC[i3]) { sC[i3] = sC[i3] * ex2f_(mC[i3] - zb1) + 1.f; mC[i3] = zb1; }
                    else sC[i3] += ex2f_(zb1 - mC[i3]);
                }
            }
            float2* op = &dColPart[bid][t * 16];
#pragma unroll
            for (int k = 0; k < 16; k++) { float2 v; v.x = mC[k]; v.y = sC[k]; op[k] = v; }
        }
        grid_barrier();

        // ---- combine phase: every block reduces 16 columns over 128 bands ----
        {
            int c0 = bid * 16;
            int band = t & 127, g = t >> 7;       // g in {0,1}: col sub-group
            float2 P[8];
#pragma unroll
            for (int k = 0; k < 8; k++) P[k] = __ldcg(&dColPart[band][c0 + g * 8 + k]);
#pragma unroll
            for (int o = 16; o; o >>= 1) {
#pragma unroll
                for (int k = 0; k < 8; k++) {
                    float mo = __shfl_xor_sync(0xffffffffu, P[k].x, o);
                    float so = __shfl_xor_sync(0xffffffffu, P[k].y, o);
                    lse_comb(P[k], mo, so);
                }
            }
            if (lane == 0) {
#pragma unroll
                for (int k = 0; k < 8; k++) comb[w][k] = P[k];
            }
            __syncthreads();
            if (t < 16) {
                int j = t & 7, g2 = t >> 3;       // warps g2*4..g2*4+3 share group g2
                float2 acc = comb[g2 * 4][j];
                lse_comb(acc, comb[g2 * 4 + 1][j].x, comb[g2 * 4 + 1][j].y);
                lse_comb(acc, comb[g2 * 4 + 2][j].x, comb[g2 * 4 + 2][j].y);
                lse_comb(acc, comb[g2 * 4 + 3][j].x, comb[g2 * 4 + 3][j].y);
                int col = c0 + g2 * 8 + j;
                float gt = -el2 * (acc.x + lg2f_(acc.y));
                if (fin) {
                    dFin[1][col] = gt;
                } else {
                    if (avg) gt = 0.5f * (__ldcg(&dF[rd][1][col]) + gt);
                    dF[rd ^ 1][1][col] = gt;
                }
            }
        }
        grid_barrier();
    }

    // ---- final reduction ----
    if (bid == 0) {
        float s = 0.f;
        for (int i = t; i < NPTS; i += 256)
            s += (__ldcg(&dFin[0][i]) - __ldcg(&dFin[2][i])) +
                 (__ldcg(&dFin[1][i]) - __ldcg(&dFin[3][i]));
#pragma unroll
        for (int o = 16; o; o >>= 1) s += __shfl_xor_sync(0xffffffffu, s, o);
        __shared__ float smr[8];
        if (lane == 0) smr[w] = s;
        __syncthreads();
        if (t == 0) {
            float tot = 0.f;
            for (int k = 0; k < 8; k++) tot += smr[k];
            out[0] = tot * (1.0f / NPTS);
        }
    }
}

// ---------------- launch ----------------
extern "C" void kernel_launch(void* const* d_in, const int* in_sizes, int n_in,
                              void* d_out, int out_size) {
    const float* x = (const float*)d_in[0];
    const float* y = (const float*)d_in[1];
    float* out = (float*)d_out;

    prep_k<<<128, 256>>>(x, y);                 // 1
    sched_k<<<1, 64>>>();                       // 2
    gemm_cost<<<3 * 1024, 256>>>(x, y);         // 3
    conv_k<<<3 * 8192, 256>>>();                // 4
    sinkhorn_k<<<NB, 256>>>(out);               // 5  (ncu -s 5 lands past this; loop visible)
}

// round 12
// speedup vs baseline: 1.0598x; 1.0598x over previous
#include <cuda_runtime.h>
#include <cuda_fp16.h>
#include <math.h>

#define NPTS 4096
#define DIMS 64
#define MAX_ITERS 44
#define NB 512                       /* persistent grid; occupancy-4 guaranteed */
#define NEGLOGN (-8.317766166719343f)
#define LN2f 0.6931471805599453f
#define INVLN2f 1.4426950408889634f
#define C0Z (NEGLOGN * INVLN2f)

// ---------------- static device scratch ----------------
__device__ float dCxy[(size_t)NPTS * NPTS];
__device__ float dCxx[(size_t)NPTS * NPTS];
__device__ float dCyy[(size_t)NPTS * NPTS];
__device__ __align__(16) __half hCxy[(size_t)NPTS * NPTS];
__device__ __align__(16) __half hCyx[(size_t)NPTS * NPTS];
__device__ __align__(16) __half hCxx[(size_t)NPTS * NPTS];
__device__ __align__(16) __half hCyy[(size_t)NPTS * NPTS];
// [0] Cxy row mins, [1] Cxy col mins (= Cyx row mins), [2] Cxx, [3] Cyy
__device__ float dRmin[4][NPTS];
__device__ float dX2[NPTS];
__device__ float dY2[NPTS];
__device__ float dMinP[128 * DIMS];
__device__ float dMaxP[128 * DIMS];
// slots: 0=f_ba, 1=g_ab, 2=f_aa, 3=g_bb
__device__ float dF[2][4][NPTS];
__device__ float dFin[4][NPTS];
__device__ int dBestC[4][NPTS / 2];      // per row-pair: chunk holding last max
__device__ unsigned int dBarCnt;
__device__ volatile unsigned int dBarGen;

// ---------------- helpers ----------------
__device__ __forceinline__ float ex2f_(float x) {
    float r; asm("ex2.approx.ftz.f32 %0, %1;" : "=f"(r) : "f"(x)); return r;
}
__device__ __forceinline__ float lg2f_(float x) {
    float r; asm("lg2.approx.ftz.f32 %0, %1;" : "=f"(r) : "f"(x)); return r;
}
__device__ __forceinline__ void atomicMinFloat(float* addr, float v) {
    int* ai = (int*)addr;
    int old = *ai;
    while (__int_as_float(old) > v) {
        int assumed = old;
        old = atomicCAS(ai, assumed, __float_as_int(v));
        if (old == assumed) break;
    }
}
__device__ __forceinline__ const __half* seg_M(int s) {
    return (s == 0) ? hCxy : (s == 1) ? hCyx : (s == 2) ? hCxx : hCyy;
}
__device__ __forceinline__ int hslot(int s) {
    return (s == 0) ? 1 : (s == 1) ? 0 : s;
}

// ---------------- 1) prep: inits + minmax partials + row norms ----------------
__global__ void __launch_bounds__(256) prep_k(const float* __restrict__ x,
                                              const float* __restrict__ y) {
    int t = threadIdx.x, b = blockIdx.x;  // 128 x 256
    int gi = b * 256 + t;
    if (gi < 4 * NPTS) ((float*)dRmin)[gi] = INFINITY;
    if (gi < 4 * (NPTS / 2)) ((int*)dBestC)[gi] = 0;
    if (gi == 0) dBarCnt = 0;

    int dim = t & 63, sub = t >> 6;
    float mn = INFINITY, mx = -INFINITY;
    for (int row = b * 4 + sub; row < 2 * NPTS; row += 128 * 4) {
        const float* p = (row < NPTS) ? (x + (size_t)row * DIMS)
                                      : (y + (size_t)(row - NPTS) * DIMS);
        float v = p[dim];
        mn = fminf(mn, v); mx = fmaxf(mx, v);
    }
    __shared__ float smn[256], smx[256];
    smn[t] = mn; smx[t] = mx;
    __syncthreads();
    if (t < 64) {
        mn = fminf(fminf(smn[t], smn[t + 64]), fminf(smn[t + 128], smn[t + 192]));
        mx = fmaxf(fmaxf(smx[t], smx[t + 64]), fmaxf(smx[t + 128], smx[t + 192]));
        dMinP[b * 64 + t] = mn;
        dMaxP[b * 64 + t] = mx;
    }

    int row = b * 64 + (t >> 2), q = t & 3;
    const float* p = (row < NPTS) ? (x + (size_t)row * DIMS)
                                  : (y + (size_t)(row - NPTS) * DIMS);
    float s = 0.f;
#pragma unroll
    for (int k = 0; k < 4; k++) {
        float4 v = ((const float4*)p)[q * 4 + k];
        s += v.x * v.x + v.y * v.y + v.z * v.z + v.w * v.w;
    }
    s += __shfl_xor_sync(0xffffffffu, s, 1);
    s += __shfl_xor_sync(0xffffffffu, s, 2);
    if (q == 0) {
        if (row < NPTS) dX2[row] = s; else dY2[row - NPTS] = s;
    }
}

// ---------------- 2) cost matrices + per-row/col mins ----------------
__global__ void __launch_bounds__(256) gemm_cost(const float* __restrict__ x,
                                                 const float* __restrict__ y) {
    int seg  = blockIdx.x >> 10;
    int tile = blockIdx.x & 1023;
    int bm = tile >> 5, bn = tile & 31;
    const float *A, *B, *a2, *b2;
    float* Cc;
    if (seg == 0)      { A = x; B = y; a2 = dX2; b2 = dY2; Cc = dCxy; }
    else if (seg == 1) { A = x; B = x; a2 = dX2; b2 = dX2; Cc = dCxx; }
    else               { A = y; B = y; a2 = dY2; b2 = dY2; Cc = dCyy; }

    __shared__ float As[32][128];
    __shared__ float Bs[32][128];
    __shared__ float redR[128][16];
    __shared__ float redC[128][16];
    int t = threadIdx.x;
    int m0 = bm * 128, n0 = bn * 128;
    int tm = t >> 4, tn = t & 15;

    float acc[8][8];
#pragma unroll
    for (int i = 0; i < 8; i++)
#pragma unroll
        for (int j = 0; j < 8; j++) acc[i][j] = 0.f;

    for (int kc = 0; kc < 2; kc++) {
#pragma unroll
        for (int l = 0; l < 4; l++) {
            int lin = t + l * 256;
            int r  = lin >> 3;
            int kq = (lin & 7) << 2;
            float4 va = *(const float4*)(A + (size_t)(m0 + r) * DIMS + kc * 32 + kq);
            As[kq + 0][r] = va.x; As[kq + 1][r] = va.y;
            As[kq + 2][r] = va.z; As[kq + 3][r] = va.w;
            float4 vb = *(const float4*)(B + (size_t)(n0 + r) * DIMS + kc * 32 + kq);
            Bs[kq + 0][r] = vb.x; Bs[kq + 1][r] = vb.y;
            Bs[kq + 2][r] = vb.z; Bs[kq + 3][r] = vb.w;
        }
        __syncthreads();
#pragma unroll 8
        for (int k = 0; k < 32; k++) {
            float ar[8], br[8];
#pragma unroll
            for (int i = 0; i < 4; i++) {
                ar[i]     = As[k][tm * 4 + i];
                ar[4 + i] = As[k][64 + tm * 4 + i];
                br[i]     = Bs[k][tn * 4 + i];
                br[4 + i] = Bs[k][64 + tn * 4 + i];
            }
#pragma unroll
            for (int i = 0; i < 8; i++)
#pragma unroll
                for (int j = 0; j < 8; j++) acc[i][j] += ar[i] * br[j];
        }
        __syncthreads();
    }

    float b2r[8];
#pragma unroll
    for (int j = 0; j < 4; j++) {
        b2r[j]     = b2[n0 + tn * 4 + j];
        b2r[4 + j] = b2[n0 + 64 + tn * 4 + j];
    }
    float cmin[8];
#pragma unroll
    for (int j = 0; j < 8; j++) cmin[j] = INFINITY;

#pragma unroll
    for (int i = 0; i < 8; i++) {
        int rl = (i < 4) ? (tm * 4 + i) : (64 + tm * 4 + (i - 4));
        int row = m0 + rl;
        float ha = 0.5f * a2[row];
        float4 v0, v1;
        v0.x = ha + 0.5f * b2r[0] - acc[i][0];
        v0.y = ha + 0.5f * b2r[1] - acc[i][1];
        v0.z = ha + 0.5f * b2r[2] - acc[i][2];
        v0.w = ha + 0.5f * b2r[3] - acc[i][3];
        v1.x = ha + 0.5f * b2r[4] - acc[i][4];
        v1.y = ha + 0.5f * b2r[5] - acc[i][5];
        v1.z = ha + 0.5f * b2r[6] - acc[i][6];
        v1.w = ha + 0.5f * b2r[7] - acc[i][7];
        *(float4*)(Cc + (size_t)row * NPTS + n0 + tn * 4)      = v0;
        *(float4*)(Cc + (size_t)row * NPTS + n0 + 64 + tn * 4) = v1;
        float rm = fminf(fminf(fminf(v0.x, v0.y), fminf(v0.z, v0.w)),
                         fminf(fminf(v1.x, v1.y), fminf(v1.z, v1.w)));
        redR[rl][tn] = rm;
        cmin[0] = fminf(cmin[0], v0.x); cmin[1] = fminf(cmin[1], v0.y);
        cmin[2] = fminf(cmin[2], v0.z); cmin[3] = fminf(cmin[3], v0.w);
        cmin[4] = fminf(cmin[4], v1.x); cmin[5] = fminf(cmin[5], v1.y);
        cmin[6] = fminf(cmin[6], v1.z); cmin[7] = fminf(cmin[7], v1.w);
    }
#pragma unroll
    for (int j = 0; j < 8; j++) {
        int cl = (j < 4) ? (tn * 4 + j) : (64 + tn * 4 + (j - 4));
        redC[cl][tm] = cmin[j];
    }
    __syncthreads();
    if (t < 128) {
        float r = INFINITY, c = INFINITY;
#pragma unroll
        for (int k = 0; k < 16; k++) { r = fminf(r, redR[t][k]); c = fminf(c, redC[t][k]); }
        if (seg == 0) {
            atomicMinFloat(&dRmin[0][m0 + t], r);
            atomicMinFloat(&dRmin[1][n0 + t], c);
        } else if (seg == 1) {
            atomicMinFloat(&dRmin[2][m0 + t], r);
        } else {
            atomicMinFloat(&dRmin[3][m0 + t], r);
        }
    }
}

// ---------------- 3) conversions (straight x3 + transposed), one launch ----------------
__global__ void __launch_bounds__(256) conv_all_k() {
    int b = blockIdx.x;
    if (b < 3 * 8192) {
        int seg3  = b >> 13;
        int local = b & 8191;
        const float* C = (seg3 == 0) ? dCxy : (seg3 == 1) ? dCxx : dCyy;
        __half* H = (seg3 == 0) ? hCxy : (seg3 == 1) ? hCxx : hCyy;
        const float* rmin = (seg3 == 0) ? dRmin[0] : (seg3 == 1) ? dRmin[2] : dRmin[3];
        size_t idx = (size_t)local * 2048 + threadIdx.x * 8;
        int row = (int)(idx >> 12);
        float rm = rmin[row];
        float4 a = *(const float4*)(C + idx);
        float4 bb = *(const float4*)(C + idx + 4);
        half2 q0 = __floats2half2_rn(a.x - rm, a.y - rm);
        half2 q1 = __floats2half2_rn(a.z - rm, a.w - rm);
        half2 q2 = __floats2half2_rn(bb.x - rm, bb.y - rm);
        half2 q3 = __floats2half2_rn(bb.z - rm, bb.w - rm);
        uint4 o;
        o.x = *(unsigned*)&q0; o.y = *(unsigned*)&q1;
        o.z = *(unsigned*)&q2; o.w = *(unsigned*)&q3;
        *(uint4*)(H + idx) = o;
    } else {
        // Cxy (fp32) -> hCyx (fp16 transposed, col-min relative)
        __shared__ float tile[32][33];
        int idx2 = b - 3 * 8192;                 // 0..16383
        int bx = idx2 & 127, by = idx2 >> 7;
        int x0 = bx * 32, y0 = by * 32;
        int tx = threadIdx.x & 31, ty = threadIdx.x >> 5;  // 32 x 8
#pragma unroll
        for (int j = 0; j < 32; j += 8)
            tile[ty + j][tx] = dCxy[(size_t)(y0 + ty + j) * NPTS + x0 + tx];
        __syncthreads();
#pragma unroll
        for (int j = 0; j < 32; j += 8) {
            int orow = x0 + ty + j;
            float rm = dRmin[1][orow];
            hCyx[(size_t)orow * NPTS + y0 + tx] = __float2half_rn(tile[tx][ty + j] - rm);
        }
    }
}

// ---------------- grid barrier ----------------
__device__ __forceinline__ void grid_barrier() {
    __syncthreads();
    if (threadIdx.x == 0) {
        unsigned gen = dBarGen;
        __threadfence();
        if (atomicAdd(&dBarCnt, 1) == NB - 1) {
            dBarCnt = 0;
            __threadfence();
            dBarGen = gen + 1;
        } else {
            while (dBarGen == gen) __nanosleep(64);
        }
        __threadfence();
    }
    __syncthreads();
}

// ---- row softmin: 2 rows/warp, exp2 domain, rotated chunk start + argmax track ----
__device__ __forceinline__ void lse_pair(const __half* __restrict__ Mrow0,
                                         const float* __restrict__ Hs,
                                         float negs1, int sc,
                                         float& M0o, float& S0o, float& M1o, float& S1o,
                                         int& bestC) {
    const unsigned FULL = 0xffffffffu;
    int lane = threadIdx.x & 31;
    const uint4* b0 = (const uint4*)Mrow0 + lane;
    const uint4* b1 = (const uint4*)(Mrow0 + NPTS) + lane;
    float m0 = -INFINITY, s0 = 0.f, m1 = -INFINITY, s1 = 0.f;
    float mTrk = -INFINITY; int cTrk = 0;
    int pc = sc & 15;
    uint4 A0 = __ldg(b0 + pc * 32);
    uint4 A1 = __ldg(b1 + pc * 32);
#pragma unroll 4
    for (int c = 0; c < 16; c++) {
        uint4 a0 = A0, a1 = A1;
        int cur = pc;
        pc = (pc + 1) & 15;
        if (c < 15) { A0 = __ldg(b0 + pc * 32); A1 = __ldg(b1 + pc * 32); }
        int hIdx = cur * 256 + lane * 8;
        float h[8];
        float4 hA = *(const float4*)&Hs[hIdx];
        float4 hB = *(const float4*)&Hs[hIdx + 4];
        h[0] = hA.x; h[1] = hA.y; h[2] = hA.z; h[3] = hA.w;
        h[4] = hB.x; h[5] = hB.y; h[6] = hB.z; h[7] = hB.w;
        float z0[8], z1[8];
        const half2* q0 = (const half2*)&a0;
        const half2* q1 = (const half2*)&a1;
#pragma unroll
        for (int k = 0; k < 4; k++) {
            float2 f0 = __half22float2(q0[k]);
            float2 f1 = __half22float2(q1[k]);
            z0[2 * k]     = fmaf(f0.x, negs1, h[2 * k]);
            z0[2 * k + 1] = fmaf(f0.y, negs1, h[2 * k + 1]);
            z1[2 * k]     = fmaf(f1.x, negs1, h[2 * k]);
            z1[2 * k + 1] = fmaf(f1.y, negs1, h[2 * k + 1]);
        }
        float c0m = fmaxf(fmaxf(fmaxf(z0[0], z0[1]), fmaxf(z0[2], z0[3])),
                          fmaxf(fmaxf(z0[4], z0[5]), fmaxf(z0[6], z0[7])));
        float c1m = fmaxf(fmaxf(fmaxf(z1[0], z1[1]), fmaxf(z1[2], z1[3])),
                          fmaxf(fmaxf(z1[4], z1[5]), fmaxf(z1[6], z1[7])));
        if (c0m > mTrk) { mTrk = c0m; cTrk = cur; }
        if (!__all_sync(FULL, (c0m - m0) < -64.f)) {
            if (c0m > m0) { s0 *= ex2f_(m0 - c0m); m0 = c0m; }
            float e0 = ex2f_(z0[0] - m0), e1 = ex2f_(z0[1] - m0);
            float e2 = ex2f_(z0[2] - m0), e3 = ex2f_(z0[3] - m0);
            float e4 = ex2f_(z0[4] - m0), e5 = ex2f_(z0[5] - m0);
            float e6 = ex2f_(z0[6] - m0), e7 = ex2f_(z0[7] - m0);
            s0 += ((e0 + e1) + (e2 + e3)) + ((e4 + e5) + (e6 + e7));
        }
        if (!__all_sync(FULL, (c1m - m1) < -64.f)) {
            if (c1m > m1) { s1 *= ex2f_(m1 - c1m); m1 = c1m; }
            float e0 = ex2f_(z1[0] - m1), e1 = ex2f_(z1[1] - m1);
            float e2 = ex2f_(z1[2] - m1), e3 = ex2f_(z1[3] - m1);
            float e4 = ex2f_(z1[4] - m1), e5 = ex2f_(z1[5] - m1);
            float e6 = ex2f_(z1[6] - m1), e7 = ex2f_(z1[7] - m1);
            s1 += ((e0 + e1) + (e2 + e3)) + ((e4 + e5) + (e6 + e7));
        }
        if ((c & 3) == 0) {   // broadcast early so skipping engages from chunk 1
            float w = m0;
#pragma unroll
            for (int o = 16; o; o >>= 1) w = fmaxf(w, __shfl_xor_sync(FULL, w, o));
            if (w > m0) { s0 *= ex2f_(m0 - w); m0 = w; }
            w = m1;
#pragma unroll
            for (int o = 16; o; o >>= 1) w = fmaxf(w, __shfl_xor_sync(FULL, w, o));
            if (w > m1) { s1 *= ex2f_(m1 - w); m1 = w; }
        }
    }
    // final max broadcast + sum reduce
    {
        float w = m0;
#pragma unroll
        for (int o = 16; o; o >>= 1) w = fmaxf(w, __shfl_xor_sync(FULL, w, o));
        if (w > m0) { s0 *= ex2f_(m0 - w); m0 = w; }
        w = m1;
#pragma unroll
        for (int o = 16; o; o >>= 1) w = fmaxf(w, __shfl_xor_sync(FULL, w, o));
        if (w > m1) { s1 *= ex2f_(m1 - w); m1 = w; }
    }
#pragma unroll
    for (int o = 16; o; o >>= 1) {
        s0 += __shfl_xor_sync(FULL, s0, o);
        s1 += __shfl_xor_sync(FULL, s1, o);
    }
    // warp argmax for the seed chunk
#pragma unroll
    for (int o = 16; o; o >>= 1) {
        float mo = __shfl_xor_sync(FULL, mTrk, o);
        int co = __shfl_xor_sync(FULL, cTrk, o);
        if (mo > mTrk) { mTrk = mo; cTrk = co; }
    }
    bestC = cTrk;
    M0o = m0; S0o = s0; M1o = m1; S1o = s1;
}

// ---------------- 4) persistent Sinkhorn (row-only, 4 segs) ----------------
__global__ void __launch_bounds__(256, 4) sinkhorn_k(float* __restrict__ out) {
    int bid = blockIdx.x;
    int seg = bid >> 7, bb = bid & 127;   // 128 blocks/seg, 32 rows/block
    int t = threadIdx.x, w = t >> 5, lane = t & 31;
    __shared__ __align__(16) float Hs[NPTS];
    __shared__ float sEps[MAX_ITERS];
    const __half* Mbase = seg_M(seg);
    const float* rmin = dRmin[seg];
    int hs = hslot(seg);

    // ---- inline eps schedule (every block computes it; no inter-block dep) ----
    if (t < 64) {
        float mn = INFINITY, mx = -INFINITY;
        for (int b2 = 0; b2 < 128; b2++) {
            mn = fminf(mn, dMinP[b2 * 64 + t]);
            mx = fmaxf(mx, dMaxP[b2 * 64 + t]);
        }
        float r = mx - mn;
        Hs[t] = r * r;
    }
    __syncthreads();
    if (t == 0) {
        float d2 = 0.f;
        for (int d = 0; d < 64; d++) d2 += Hs[d];
        Hs[64] = sqrtf(d2);
    }
    __syncthreads();
    float diam = Hs[64];
    double start = 2.0 * log((double)diam);
    double stop  = 2.0 * log(0.05);
    double step  = 2.0 * log(0.8);
    double cnt = ceil((stop - start) / step);
    int n_ar = (cnt > 0.0) ? (int)cnt : 0;
    if (n_ar > MAX_ITERS - 2) n_ar = MAX_ITERS - 2;
    int n = n_ar + 2;
    if (t < MAX_ITERS) {
        sEps[t] = (t == 0) ? diam * diam
                : ((t - 1 < n_ar) ? (float)exp(start + (double)(t - 1) * step) : 0.0025f);
    }
    __syncthreads();

    // ---- unified pass loop: 0 = init, 1..n = annealing, n+1 = final extrapolation ----
    for (int pass = 0; pass <= n + 1; pass++) {
        float eps = (pass == 0) ? sEps[0] : ((pass <= n) ? sEps[pass - 1] : 0.0025f);
        float s1f = (1.f / eps) * INVLN2f;
        float el2 = eps * LN2f;
        int rd = pass & 1;
        bool avg = (pass >= 1 && pass <= n);
        bool fin = (pass == n + 1);

        if (pass == 0) {
            for (int i = t * 4; i < NPTS; i += 1024) {
                float4 o; o.x = C0Z; o.y = C0Z; o.z = C0Z; o.w = C0Z;
                *(float4*)&Hs[i] = o;
            }
        } else {
            const float4* Hv = (const float4*)dF[rd][hs];
            for (int i = t; i < NPTS / 4; i += 256) {
                float4 hv = __ldcg(&Hv[i]);
                float4 o;
                o.x = fmaf(hv.x, s1f, C0Z); o.y = fmaf(hv.y, s1f, C0Z);
                o.z = fmaf(hv.z, s1f, C0Z); o.w = fmaf(hv.w, s1f, C0Z);
                *(float4*)&Hs[i * 4] = o;
            }
        }
        __syncthreads();

#pragma unroll
        for (int rp = 0; rp < 2; rp++) {
            int row0 = bb * 32 + rp * 16 + w * 2;
            int pairI = row0 >> 1;
            int sc = dBestC[seg][pairI];
            float m0, s0, m1, s1;
            int bc;
            lse_pair(Mbase + (size_t)row0 * NPTS, Hs, -s1f, sc, m0, s0, m1, s1, bc);
            if (lane == 0) {
                dBestC[seg][pairI] = bc;
                float ft0 = rmin[row0]     - el2 * (m0 + lg2f_(s0));
                float ft1 = rmin[row0 + 1] - el2 * (m1 + lg2f_(s1));
                if (fin) {
                    dFin[seg][row0]     = ft0;
                    dFin[seg][row0 + 1] = ft1;
                } else {
                    if (avg) {
                        ft0 = 0.5f * (__ldcg(&dF[rd][seg][row0])     + ft0);
                        ft1 = 0.5f * (__ldcg(&dF[rd][seg][row0 + 1]) + ft1);
                    }
                    dF[rd ^ 1][seg][row0]     = ft0;
                    dF[rd ^ 1][seg][row0 + 1] = ft1;
                }
            }
        }
        grid_barrier();
    }

    // ---- final reduction ----
    if (bid == 0) {
        float s = 0.f;
        for (int i = t; i < NPTS; i += 256)
            s += (__ldcg(&dFin[0][i]) - __ldcg(&dFin[2][i])) +
                 (__ldcg(&dFin[1][i]) - __ldcg(&dFin[3][i]));
#pragma unroll
        for (int o = 16; o; o >>= 1) s += __shfl_xor_sync(0xffffffffu, s, o);
        __shared__ float smr[8];
        if (lane == 0) smr[w] = s;
        __syncthreads();
        if (t == 0) {
            float tot = 0.f;
            for (int k = 0; k < 8; k++) tot += smr[k];
            out[0] = tot * (1.0f / NPTS);
        }
    }
}

// ---------------- launch ----------------
extern "C" void kernel_launch(void* const* d_in, const int* in_sizes, int n_in,
                              void* d_out, int out_size) {
    const float* x = (const float*)d_in[0];
    const float* y = (const float*)d_in[1];
    float* out = (float*)d_out;

    prep_k<<<128, 256>>>(x, y);                     // 1
    gemm_cost<<<3 * 1024, 256>>>(x, y);             // 2
    conv_all_k<<<3 * 8192 + 16384, 256>>>();        // 3
    sinkhorn_k<<<NB, 256>>>(out);                   // 4  <- profiled slot
}

// round 14
// speedup vs baseline: 1.2359x; 1.1662x over previous
#include <cuda_runtime.h>
#include <cuda_fp16.h>
#include <math.h>

#define NPTS 4096
#define DIMS 64
#define MAX_ITERS 44
#define NB 512                       /* persistent grid; occupancy-4 guaranteed */
#define NEGLOGN (-8.317766166719343f)
#define LN2f 0.6931471805599453f
#define INVLN2f 1.4426950408889634f
#define C0Z (NEGLOGN * INVLN2f)

typedef unsigned long long ull;

// ---------------- static device scratch ----------------
__device__ float dCxy[(size_t)NPTS * NPTS];
__device__ float dCxx[(size_t)NPTS * NPTS];
__device__ float dCyy[(size_t)NPTS * NPTS];
__device__ __align__(16) __half hCxy[(size_t)NPTS * NPTS];
__device__ __align__(16) __half hCyx[(size_t)NPTS * NPTS];
__device__ __align__(16) __half hCxx[(size_t)NPTS * NPTS];
__device__ __align__(16) __half hCyy[(size_t)NPTS * NPTS];
// [0] Cxy row mins, [1] Cxy col mins (= Cyx row mins), [2] Cxx, [3] Cyy
__device__ float dRmin[4][NPTS];
__device__ float dX2[NPTS];
__device__ float dY2[NPTS];
__device__ float dMinP[128 * DIMS];
__device__ float dMaxP[128 * DIMS];
__device__ float dEps[MAX_ITERS];
__device__ int   dNeps;
// slots: 0=f_ba, 1=g_ab, 2=f_aa, 3=g_bb
__device__ float dF[2][4][NPTS];
__device__ float dFin[4][NPTS];
__device__ unsigned int dBarCnt;
__device__ volatile unsigned int dBarGen;

// ---------------- helpers ----------------
__device__ __forceinline__ float ex2f_(float x) {
    float r; asm("ex2.approx.ftz.f32 %0, %1;" : "=f"(r) : "f"(x)); return r;
}
__device__ __forceinline__ float lg2f_(float x) {
    float r; asm("lg2.approx.ftz.f32 %0, %1;" : "=f"(r) : "f"(x)); return r;
}
__device__ __forceinline__ void atomicMinFloat(float* addr, float v) {
    int* ai = (int*)addr;
    int old = *ai;
    while (__int_as_float(old) > v) {
        int assumed = old;
        old = atomicCAS(ai, assumed, __float_as_int(v));
        if (old == assumed) break;
    }
}
__device__ __forceinline__ const __half* seg_M(int s) {
    return (s == 0) ? hCxy : (s == 1) ? hCyx : (s == 2) ? hCxx : hCyy;
}
__device__ __forceinline__ int hslot(int s) {
    return (s == 0) ? 1 : (s == 1) ? 0 : s;
}
// f32x2 packed helpers
__device__ __forceinline__ ull dupf2_(float a) {
    ull r; asm("mov.b64 %0, {%1, %1};" : "=l"(r) : "f"(a)); return r;
}
__device__ __forceinline__ void fma2_(ull& d, ull a, ull b) {
    asm("fma.rn.f32x2 %0, %1, %2, %0;" : "+l"(d) : "l"(a), "l"(b));
}
__device__ __forceinline__ void unpack2_(ull p, float& lo, float& hi) {
    asm("mov.b64 {%0, %1}, %2;" : "=f"(lo), "=f"(hi) : "l"(p));
}

// ---------------- 1) prep: init dRmin + minmax partials + row norms ----------------
__global__ void __launch_bounds__(256) prep_k(const float* __restrict__ x,
                                              const float* __restrict__ y) {
    int t = threadIdx.x, b = blockIdx.x;  // 128 blocks x 256 threads
    int gi = b * 256 + t;
    if (gi < 4 * NPTS) ((float*)dRmin)[gi] = INFINITY;

    int dim = t & 63, sub = t >> 6;
    float mn = INFINITY, mx = -INFINITY;
    for (int row = b * 4 + sub; row < 2 * NPTS; row += 128 * 4) {
        const float* p = (row < NPTS) ? (x + (size_t)row * DIMS)
                                      : (y + (size_t)(row - NPTS) * DIMS);
        float v = p[dim];
        mn = fminf(mn, v); mx = fmaxf(mx, v);
    }
    __shared__ float smn[256], smx[256];
    smn[t] = mn; smx[t] = mx;
    __syncthreads();
    if (t < 64) {
        mn = fminf(fminf(smn[t], smn[t + 64]), fminf(smn[t + 128], smn[t + 192]));
        mx = fmaxf(fmaxf(smx[t], smx[t + 64]), fmaxf(smx[t + 128], smx[t + 192]));
        dMinP[b * 64 + t] = mn;
        dMaxP[b * 64 + t] = mx;
    }

    int row = b * 64 + (t >> 2), q = t & 3;
    const float* p = (row < NPTS) ? (x + (size_t)row * DIMS)
                                  : (y + (size_t)(row - NPTS) * DIMS);
    float s = 0.f;
#pragma unroll
    for (int k = 0; k < 4; k++) {
        float4 v = ((const float4*)p)[q * 4 + k];
        s += v.x * v.x + v.y * v.y + v.z * v.z + v.w * v.w;
    }
    s += __shfl_xor_sync(0xffffffffu, s, 1);
    s += __shfl_xor_sync(0xffffffffu, s, 2);
    if (q == 0) {
        if (row < NPTS) dX2[row] = s; else dY2[row - NPTS] = s;
    }
}

// ---------------- 2) cost matrices (f32x2 FFMA2) + row/col mins; block 3072 = sched ----------------
__global__ void __launch_bounds__(256) gemm_cost(const float* __restrict__ x,
                                                 const float* __restrict__ y) {
    __shared__ float As[32][128];
    __shared__ float Bs[32][128];
    __shared__ float redR[128][16];
    __shared__ float redC[128][16];
    int t = threadIdx.x;

    // ---- dedicated schedule block (hidden under the 3072 GEMM blocks) ----
    if (blockIdx.x == 3072) {
        float* sr2 = &As[0][0];       // reuse smem
        if (t < 64) {
            float mn = INFINITY, mx = -INFINITY;
#pragma unroll 8
            for (int b = 0; b < 128; b++) {
                mn = fminf(mn, dMinP[b * 64 + t]);
                mx = fmaxf(mx, dMaxP[b * 64 + t]);
            }
            float r = mx - mn;
            sr2[t] = r * r;
        }
        __syncthreads();
        if (t == 0) {
            float d2 = 0.f;
            for (int d = 0; d < 64; d++) d2 += sr2[d];
            sr2[64] = sqrtf(d2);
        }
        __syncthreads();
        float diam = sr2[64];
        double start = 2.0 * log((double)diam);
        double stop  = 2.0 * log(0.05);
        double step  = 2.0 * log(0.8);
        double cnt = ceil((stop - start) / step);
        int n_ar = (cnt > 0.0) ? (int)cnt : 0;
        if (n_ar > MAX_ITERS - 2) n_ar = MAX_ITERS - 2;
        if (t == 0) { dEps[0] = diam * diam; dNeps = n_ar + 2; dBarCnt = 0; }
        if (t >= 1 && t < MAX_ITERS) {
            int k = t - 1;
            dEps[t] = (k < n_ar) ? (float)exp(start + (double)k * step) : 0.0025f;
        }
        return;
    }

    int seg  = blockIdx.x >> 10;
    int tile = blockIdx.x & 1023;
    int bm = tile >> 5, bn = tile & 31;
    const float *A, *B, *a2, *b2;
    float* Cc;
    if (seg == 0)      { A = x; B = y; a2 = dX2; b2 = dY2; Cc = dCxy; }
    else if (seg == 1) { A = x; B = x; a2 = dX2; b2 = dX2; Cc = dCxx; }
    else               { A = y; B = y; a2 = dY2; b2 = dY2; Cc = dCyy; }

    int m0 = bm * 128, n0 = bn * 128;
    int tm = t >> 4, tn = t & 15;

    // packed accumulators: acc2[i][0..1] = cols (tn*4+0,1),(tn*4+2,3);
    //                      acc2[i][2..3] = cols (64+tn*4+0,1),(64+tn*4+2,3)
    ull acc2[8][4];
#pragma unroll
    for (int i = 0; i < 8; i++)
#pragma unroll
        for (int j = 0; j < 4; j++) acc2[i][j] = 0ull;

    for (int kc = 0; kc < 2; kc++) {
#pragma unroll
        for (int l = 0; l < 4; l++) {
            int lin = t + l * 256;
            int r  = lin >> 3;
            int kq = (lin & 7) << 2;
            float4 va = *(const float4*)(A + (size_t)(m0 + r) * DIMS + kc * 32 + kq);
            As[kq + 0][r] = va.x; As[kq + 1][r] = va.y;
            As[kq + 2][r] = va.z; As[kq + 3][r] = va.w;
            float4 vb = *(const float4*)(B + (size_t)(n0 + r) * DIMS + kc * 32 + kq);
            Bs[kq + 0][r] = vb.x; Bs[kq + 1][r] = vb.y;
            Bs[kq + 2][r] = vb.z; Bs[kq + 3][r] = vb.w;
        }
        __syncthreads();
#pragma unroll 8
        for (int k = 0; k < 32; k++) {
            float4 aA = *(const float4*)&As[k][tm * 4];
            float4 aB = *(const float4*)&As[k][64 + tm * 4];
            ulonglong2 bA = *(const ulonglong2*)&Bs[k][tn * 4];
            ulonglong2 bB = *(const ulonglong2*)&Bs[k][64 + tn * 4];
            ull ad[8];
            ad[0] = dupf2_(aA.x); ad[1] = dupf2_(aA.y);
            ad[2] = dupf2_(aA.z); ad[3] = dupf2_(aA.w);
            ad[4] = dupf2_(aB.x); ad[5] = dupf2_(aB.y);
            ad[6] = dupf2_(aB.z); ad[7] = dupf2_(aB.w);
#pragma unroll
            for (int i = 0; i < 8; i++) {
                fma2_(acc2[i][0], ad[i], bA.x);
                fma2_(acc2[i][1], ad[i], bA.y);
                fma2_(acc2[i][2], ad[i], bB.x);
                fma2_(acc2[i][3], ad[i], bB.y);
            }
        }
        __syncthreads();
    }

    float b2r[8];
#pragma unroll
    for (int j = 0; j < 4; j++) {
        b2r[j]     = b2[n0 + tn * 4 + j];
        b2r[4 + j] = b2[n0 + 64 + tn * 4 + j];
    }
    float cmin[8];
#pragma unroll
    for (int j = 0; j < 8; j++) cmin[j] = INFINITY;

#pragma unroll
    for (int i = 0; i < 8; i++) {
        int rl = (i < 4) ? (tm * 4 + i) : (64 + tm * 4 + (i - 4));
        int row = m0 + rl;
        float ha = 0.5f * a2[row];
        float a0, a1, a2v, a3, a4, a5, a6, a7;
        unpack2_(acc2[i][0], a0, a1);
        unpack2_(acc2[i][1], a2v, a3);
        unpack2_(acc2[i][2], a4, a5);
        unpack2_(acc2[i][3], a6, a7);
        float4 v0, v1;
        v0.x = ha + 0.5f * b2r[0] - a0;
        v0.y = ha + 0.5f * b2r[1] - a1;
        v0.z = ha + 0.5f * b2r[2] - a2v;
        v0.w = ha + 0.5f * b2r[3] - a3;
        v1.x = ha + 0.5f * b2r[4] - a4;
        v1.y = ha + 0.5f * b2r[5] - a5;
        v1.z = ha + 0.5f * b2r[6] - a6;
        v1.w = ha + 0.5f * b2r[7] - a7;
        *(float4*)(Cc + (size_t)row * NPTS + n0 + tn * 4)      = v0;
        *(float4*)(Cc + (size_t)row * NPTS + n0 + 64 + tn * 4) = v1;
        float rm = fminf(fminf(fminf(v0.x, v0.y), fminf(v0.z, v0.w)),
                         fminf(fminf(v1.x, v1.y), fminf(v1.z, v1.w)));
        redR[rl][tn] = rm;
        cmin[0] = fminf(cmin[0], v0.x); cmin[1] = fminf(cmin[1], v0.y);
        cmin[2] = fminf(cmin[2], v0.z); cmin[3] = fminf(cmin[3], v0.w);
        cmin[4] = fminf(cmin[4], v1.x); cmin[5] = fminf(cmin[5], v1.y);
        cmin[6] = fminf(cmin[6], v1.z); cmin[7] = fminf(cmin[7], v1.w);
    }
#pragma unroll
    for (int j = 0; j < 8; j++) {
        int cl = (j < 4) ? (tn * 4 + j) : (64 + tn * 4 + (j - 4));
        redC[cl][tm] = cmin[j];
    }
    __syncthreads();
    if (t < 128) {
        float r = INFINITY, c = INFINITY;
#pragma unroll
        for (int k = 0; k < 16; k++) { r = fminf(r, redR[t][k]); c = fminf(c, redC[t][k]); }
        if (seg == 0) {
            atomicMinFloat(&dRmin[0][m0 + t], r);
            atomicMinFloat(&dRmin[1][n0 + t], c);
        } else if (seg == 1) {
            atomicMinFloat(&dRmin[2][m0 + t], r);
        } else {
            atomicMinFloat(&dRmin[3][m0 + t], r);
        }
    }
}

// ---------------- 3) conversions (straight x3 + transposed), one launch ----------------
__global__ void __launch_bounds__(256) conv_all_k() {
    int b = blockIdx.x;
    if (b < 3 * 8192) {
        int seg3  = b >> 13;
        int local = b & 8191;
        const float* C = (seg3 == 0) ? dCxy : (seg3 == 1) ? dCxx : dCyy;
        __half* H = (seg3 == 0) ? hCxy : (seg3 == 1) ? hCxx : hCyy;
        const float* rmin = (seg3 == 0) ? dRmin[0] : (seg3 == 1) ? dRmin[2] : dRmin[3];
        size_t idx = (size_t)local * 2048 + threadIdx.x * 8;
        int row = (int)(idx >> 12);
        float rm = rmin[row];
        float4 a = *(const float4*)(C + idx);
        float4 bb = *(const float4*)(C + idx + 4);
        half2 q0 = __floats2half2_rn(a.x - rm, a.y - rm);
        half2 q1 = __floats2half2_rn(a.z - rm, a.w - rm);
        half2 q2 = __floats2half2_rn(bb.x - rm, bb.y - rm);
        half2 q3 = __floats2half2_rn(bb.z - rm, bb.w - rm);
        uint4 o;
        o.x = *(unsigned*)&q0; o.y = *(unsigned*)&q1;
        o.z = *(unsigned*)&q2; o.w = *(unsigned*)&q3;
        *(uint4*)(H + idx) = o;
    } else {
        __shared__ float tile[32][33];
        int idx2 = b - 3 * 8192;                 // 0..16383
        int bx = idx2 & 127, by = idx2 >> 7;
        int x0 = bx * 32, y0 = by * 32;
        int tx = threadIdx.x & 31, ty = threadIdx.x >> 5;  // 32 x 8
#pragma unroll
        for (int j = 0; j < 32; j += 8)
            tile[ty + j][tx] = dCxy[(size_t)(y0 + ty + j) * NPTS + x0 + tx];
        __syncthreads();
#pragma unroll
        for (int j = 0; j < 32; j += 8) {
            int orow = x0 + ty + j;
            float rm = dRmin[1][orow];
            hCyx[(size_t)orow * NPTS + y0 + tx] = __float2half_rn(tile[tx][ty + j] - rm);
        }
    }
}

// ---------------- grid barrier (all NB blocks resident by construction) ----------------
__device__ __forceinline__ void grid_barrier() {
    __syncthreads();
    if (threadIdx.x == 0) {
        unsigned gen = dBarGen;
        __threadfence();
        if (atomicAdd(&dBarCnt, 1) == NB - 1) {
            dBarCnt = 0;
            __threadfence();
            dBarGen = gen + 1;
        } else {
            while (dBarGen == gen) __nanosleep(64);
        }
        __threadfence();
    }
    __syncthreads();
}

// ---------------- softmin core: 2 rows per warp, exp2-domain, prefetched (R5 verbatim) ----------------
template <bool HAS_H>
__device__ __forceinline__ void lse_pair(const __half* __restrict__ Mrow0,
                                         const float* __restrict__ Hs,
                                         float negs1,
                                         float& M0o, float& S0o, float& M1o, float& S1o) {
    const unsigned FULL = 0xffffffffu;
    int lane = threadIdx.x & 31;
    const uint4* p0 = (const uint4*)Mrow0 + lane;
    const uint4* p1 = (const uint4*)(Mrow0 + NPTS) + lane;
    float m0 = -INFINITY, s0 = 0.f, m1 = -INFINITY, s1 = 0.f;
    uint4 A0 = __ldg(p0);
    uint4 A1 = __ldg(p1);
    int hIdx = lane * 8;
#pragma unroll 4
    for (int c = 0; c < 16; c++) {
        uint4 a0 = A0, a1 = A1;
        if (c < 15) { p0 += 32; p1 += 32; A0 = __ldg(p0); A1 = __ldg(p1); }
        float h[8];
        if (HAS_H) {
            float4 hA = *(const float4*)&Hs[hIdx];
            float4 hB = *(const float4*)&Hs[hIdx + 4];
            h[0] = hA.x; h[1] = hA.y; h[2] = hA.z; h[3] = hA.w;
            h[4] = hB.x; h[5] = hB.y; h[6] = hB.z; h[7] = hB.w;
        } else {
#pragma unroll
            for (int k = 0; k < 8; k++) h[k] = C0Z;
        }
        hIdx += 256;
        float z0[8], z1[8];
        const half2* q0 = (const half2*)&a0;
        const half2* q1 = (const half2*)&a1;
#pragma unroll
        for (int k = 0; k < 4; k++) {
            float2 f0 = __half22float2(q0[k]);
            float2 f1 = __half22float2(q1[k]);
            z0[2 * k]     = fmaf(f0.x, negs1, h[2 * k]);
            z0[2 * k + 1] = fmaf(f0.y, negs1, h[2 * k + 1]);
            z1[2 * k]     = fmaf(f1.x, negs1, h[2 * k]);
            z1[2 * k + 1] = fmaf(f1.y, negs1, h[2 * k + 1]);
        }
        float c0m = fmaxf(fmaxf(fmaxf(z0[0], z0[1]), fmaxf(z0[2], z0[3])),
                          fmaxf(fmaxf(z0[4], z0[5]), fmaxf(z0[6], z0[7])));
        float c1m = fmaxf(fmaxf(fmaxf(z1[0], z1[1]), fmaxf(z1[2], z1[3])),
                          fmaxf(fmaxf(z1[4], z1[5]), fmaxf(z1[6], z1[7])));
        if (!__all_sync(FULL, (c0m - m0) < -64.f)) {
            if (c0m > m0) { s0 *= ex2f_(m0 - c0m); m0 = c0m; }
            float e0 = ex2f_(z0[0] - m0), e1 = ex2f_(z0[1] - m0);
            float e2 = ex2f_(z0[2] - m0), e3 = ex2f_(z0[3] - m0);
            float e4 = ex2f_(z0[4] - m0), e5 = ex2f_(z0[5] - m0);
            float e6 = ex2f_(z0[6] - m0), e7 = ex2f_(z0[7] - m0);
            s0 += ((e0 + e1) + (e2 + e3)) + ((e4 + e5) + (e6 + e7));
        }
        if (!__all_sync(FULL, (c1m - m1) < -64.f)) {
            if (c1m > m1) { s1 *= ex2f_(m1 - c1m); m1 = c1m; }
            float e0 = ex2f_(z1[0] - m1), e1 = ex2f_(z1[1] - m1);
            float e2 = ex2f_(z1[2] - m1), e3 = ex2f_(z1[3] - m1);
            float e4 = ex2f_(z1[4] - m1), e5 = ex2f_(z1[5] - m1);
            float e6 = ex2f_(z1[6] - m1), e7 = ex2f_(z1[7] - m1);
            s1 += ((e0 + e1) + (e2 + e3)) + ((e4 + e5) + (e6 + e7));
        }
        if ((c & 3) == 3) {
            float w = m0;
#pragma unroll
            for (int o = 16; o; o >>= 1) w = fmaxf(w, __shfl_xor_sync(FULL, w, o));
            if (w > m0) { s0 *= ex2f_(m0 - w); m0 = w; }
            w = m1;
#pragma unroll
            for (int o = 16; o; o >>= 1) w = fmaxf(w, __shfl_xor_sync(FULL, w, o));
            if (w > m1) { s1 *= ex2f_(m1 - w); m1 = w; }
        }
    }
#pragma unroll
    for (int o = 16; o; o >>= 1) {
        s0 += __shfl_xor_sync(FULL, s0, o);
        s1 += __shfl_xor_sync(FULL, s1, o);
    }
    M0o = m0; S0o = s0; M1o = m1; S1o = s1;
}

// ---------------- 4) persistent Sinkhorn: init + loop + final + reduce (R5 verbatim) ----------------
__global__ void __launch_bounds__(256, 4) sinkhorn_k(float* __restrict__ out) {
    int bid = blockIdx.x;
    int seg = bid >> 7, bb = bid & 127;   // 128 blocks/seg, 32 rows/block
    int t = threadIdx.x, w = t >> 5, lane = t & 31;
    __shared__ __align__(16) float Hs[NPTS];
    const __half* Mbase = seg_M(seg);
    const float* rmin = dRmin[seg];
    int n = dNeps;

    // ---- init pass: eps0, H = log-weights only ----
    {
        float eps = dEps[0];
        float negs1 = -(1.f / eps) * INVLN2f;
        float el2 = eps * LN2f;
#pragma unroll
        for (int rp = 0; rp < 2; rp++) {
            int row0 = bb * 32 + rp * 16 + w * 2;
            float m0, s0, m1, s1;
            lse_pair<false>(Mbase + (size_t)row0 * NPTS, nullptr, negs1, m0, s0, m1, s1);
            if (lane == 0) {
                dF[0][seg][row0]     = rmin[row0]     - el2 * (m0 + lg2f_(s0));
                dF[0][seg][row0 + 1] = rmin[row0 + 1] - el2 * (m1 + lg2f_(s1));
            }
        }
    }
    grid_barrier();

    // ---- annealing loop: exactly n data-dependent iterations ----
    for (int it = 0; it < n; it++) {
        int src = it & 1, dst = src ^ 1;
        float eps = dEps[it];
        float s1f = (1.f / eps) * INVLN2f;
        const float* Hv = dF[src][hslot(seg)];
        for (int i = t * 4; i < NPTS; i += 1024) {
            float4 hv = *(const float4*)&Hv[i];
            float4 o;
            o.x = fmaf(hv.x, s1f, C0Z); o.y = fmaf(hv.y, s1f, C0Z);
            o.z = fmaf(hv.z, s1f, C0Z); o.w = fmaf(hv.w, s1f, C0Z);
            *(float4*)&Hs[i] = o;
        }
        __syncthreads();
        float el2 = eps * LN2f;
#pragma unroll
        for (int rp = 0; rp < 2; rp++) {
            int row0 = bb * 32 + rp * 16 + w * 2;
            float m0, s0, m1, s1;
            lse_pair<true>(Mbase + (size_t)row0 * NPTS, Hs, -s1f, m0, s0, m1, s1);
            if (lane == 0) {
                float ft0 = rmin[row0]     - el2 * (m0 + lg2f_(s0));
                float ft1 = rmin[row0 + 1] - el2 * (m1 + lg2f_(s1));
                dF[dst][seg][row0]     = 0.5f * (dF[src][seg][row0]     + ft0);
                dF[dst][seg][row0 + 1] = 0.5f * (dF[src][seg][row0 + 1] + ft1);
            }
        }
        grid_barrier();
    }

    // ---- final extrapolation at eps = BLUR^P ----
    {
        int src = n & 1;
        float eps = 0.0025f;
        float s1f = (1.f / eps) * INVLN2f;
        const float* Hv = dF[src][hslot(seg)];
        for (int i = t * 4; i < NPTS; i += 1024) {
            float4 hv = *(const float4*)&Hv[i];
            float4 o;
            o.x = fmaf(hv.x, s1f, C0Z); o.y = fmaf(hv.y, s1f, C0Z);
            o.z = fmaf(hv.z, s1f, C0Z); o.w = fmaf(hv.w, s1f, C0Z);
            *(float4*)&Hs[i] = o;
        }
        __syncthreads();
        float el2 = eps * LN2f;
#pragma unroll
        for (int rp = 0; rp < 2; rp++) {
            int row0 = bb * 32 + rp * 16 + w * 2;
            float m0, s0, m1, s1;
            lse_pair<true>(Mbase + (size_t)row0 * NPTS, Hs, -s1f, m0, s0, m1, s1);
            if (lane == 0) {
                dFin[seg][row0]     = rmin[row0]     - el2 * (m0 + lg2f_(s0));
                dFin[seg][row0 + 1] = rmin[row0 + 1] - el2 * (m1 + lg2f_(s1));
            }
        }
    }
    grid_barrier();

    // ---- reduction by block 0 ----
    if (bid == 0) {
        float s = 0.f;
        for (int i = t; i < NPTS; i += 256)
            s += (dFin[0][i] - dFin[2][i]) + (dFin[1][i] - dFin[3][i]);
#pragma unroll
        for (int o = 16; o; o >>= 1) s += __shfl_xor_sync(0xffffffffu, s, o);
        __shared__ float sm[8];
        if (lane == 0) sm[w] = s;
        __syncthreads();
        if (t == 0) {
            float tot = 0.f;
            for (int k = 0; k < 8; k++) tot += sm[k];
            out[0] = tot * (1.0f / NPTS);
        }
    }
}

// ---------------- launch ----------------
extern "C" void kernel_launch(void* const* d_in, const int* in_sizes, int n_in,
                              void* d_out, int out_size) {
    const float* x = (const float*)d_in[0];
    const float* y = (const float*)d_in[1];
    float* out = (float*)d_out;

    prep_k<<<128, 256>>>(x, y);                     // 1
    gemm_cost<<<3 * 1024 + 1, 256>>>(x, y);         // 2 (block 3072 = eps schedule)
    conv_all_k<<<3 * 8192 + 16384, 256>>>();        // 3
    sinkhorn_k<<<NB, 256>>>(out);                   // 4  <- profiled slot
}

// round 16
// speedup vs baseline: 1.3169x; 1.0656x over previous
#include <cuda_runtime.h>
#include <cuda_fp16.h>
#include <math.h>

#define NPTS 4096
#define DIMS 64
#define MAX_ITERS 44
#define NB 512                       /* persistent grid; occupancy-4 guaranteed */
#define NEGLOGN (-8.317766166719343f)
#define LN2f 0.6931471805599453f
#define INVLN2f 1.4426950408889634f
#define C0Z (NEGLOGN * INVLN2f)

typedef unsigned long long ull;

// ---------------- static device scratch ----------------
__device__ float dCxy[(size_t)NPTS * NPTS];
__device__ __align__(16) __half hCxy[(size_t)NPTS * NPTS];
__device__ __align__(16) __half hCyx[(size_t)NPTS * NPTS];
__device__ __align__(16) __half hCxx[(size_t)NPTS * NPTS];
__device__ __align__(16) __half hCyy[(size_t)NPTS * NPTS];
// [0] Cxy row mins, [1] Cxy col mins (= Cyx row mins), [2]=[3]= 0 (xx/yy offset-free)
__device__ float dRmin[4][NPTS];
__device__ float dX2[NPTS];
__device__ float dY2[NPTS];
__device__ float dMinP[128 * DIMS];
__device__ float dMaxP[128 * DIMS];
__device__ float dEps[MAX_ITERS];
__device__ int   dNeps;
// slots: 0=f_ba, 1=g_ab, 2=f_aa, 3=g_bb
__device__ float dF[2][4][NPTS];
__device__ float dFin[4][NPTS];
__device__ unsigned int dBarCnt;
__device__ volatile unsigned int dBarGen;

// ---------------- helpers ----------------
__device__ __forceinline__ float ex2f_(float x) {
    float r; asm("ex2.approx.ftz.f32 %0, %1;" : "=f"(r) : "f"(x)); return r;
}
__device__ __forceinline__ float lg2f_(float x) {
    float r; asm("lg2.approx.ftz.f32 %0, %1;" : "=f"(r) : "f"(x)); return r;
}
__device__ __forceinline__ void atomicMinFloat(float* addr, float v) {
    int* ai = (int*)addr;
    int old = *ai;
    while (__int_as_float(old) > v) {
        int assumed = old;
        old = atomicCAS(ai, assumed, __float_as_int(v));
        if (old == assumed) break;
    }
}
__device__ __forceinline__ const __half* seg_M(int s) {
    return (s == 0) ? hCxy : (s == 1) ? hCyx : (s == 2) ? hCxx : hCyy;
}
__device__ __forceinline__ int hslot(int s) {
    return (s == 0) ? 1 : (s == 1) ? 0 : s;
}
// f32x2 packed helpers
__device__ __forceinline__ ull dupf2_(float a) {
    ull r; asm("mov.b64 %0, {%1, %1};" : "=l"(r) : "f"(a)); return r;
}
__device__ __forceinline__ void fma2_(ull& d, ull a, ull b) {
    asm("fma.rn.f32x2 %0, %1, %2, %0;" : "+l"(d) : "l"(a), "l"(b));
}
__device__ __forceinline__ void unpack2_(ull p, float& lo, float& hi) {
    asm("mov.b64 {%0, %1}, %2;" : "=f"(lo), "=f"(hi) : "l"(p));
}

// ---------------- 1) prep: init dRmin + minmax partials + row norms ----------------
__global__ void __launch_bounds__(256) prep_k(const float* __restrict__ x,
                                              const float* __restrict__ y) {
    int t = threadIdx.x, b = blockIdx.x;  // 128 blocks x 256 threads
    int gi = b * 256 + t;
    if (gi < 4 * NPTS) ((float*)dRmin)[gi] = (gi < 2 * NPTS) ? INFINITY : 0.f;

    int dim = t & 63, sub = t >> 6;
    float mn = INFINITY, mx = -INFINITY;
    for (int row = b * 4 + sub; row < 2 * NPTS; row += 128 * 4) {
        const float* p = (row < NPTS) ? (x + (size_t)row * DIMS)
                                      : (y + (size_t)(row - NPTS) * DIMS);
        float v = p[dim];
        mn = fminf(mn, v); mx = fmaxf(mx, v);
    }
    __shared__ float smn[256], smx[256];
    smn[t] = mn; smx[t] = mx;
    __syncthreads();
    if (t < 64) {
        mn = fminf(fminf(smn[t], smn[t + 64]), fminf(smn[t + 128], smn[t + 192]));
        mx = fmaxf(fmaxf(smx[t], smx[t + 64]), fmaxf(smx[t + 128], smx[t + 192]));
        dMinP[b * 64 + t] = mn;
        dMaxP[b * 64 + t] = mx;
    }

    int row = b * 64 + (t >> 2), q = t & 3;
    const float* p = (row < NPTS) ? (x + (size_t)row * DIMS)
                                  : (y + (size_t)(row - NPTS) * DIMS);
    float s = 0.f;
#pragma unroll
    for (int k = 0; k < 4; k++) {
        float4 v = ((const float4*)p)[q * 4 + k];
        s += v.x * v.x + v.y * v.y + v.z * v.z + v.w * v.w;
    }
    s += __shfl_xor_sync(0xffffffffu, s, 1);
    s += __shfl_xor_sync(0xffffffffu, s, 2);
    if (q == 0) {
        if (row < NPTS) dX2[row] = s; else dY2[row - NPTS] = s;
    }
}

// ---------------- 2) cost matrices ----------------
// grid: [0,1024) xy full; [1024,1552) xx upper-triangle; [1552,2080) yy upper-triangle;
// 2080 = eps schedule. xx/yy write fp16 directly (offset 0) + mirrored tile (symmetry).
#define MIRS 136   /* mirror smem stride in halves: 16B-aligned rows, 2-way conflicts */
__global__ void __launch_bounds__(256) gemm_cost(const float* __restrict__ x,
                                                 const float* __restrict__ y) {
    __shared__ __align__(16) float SB[12288];   // 48KB, manually partitioned
    float (*As)[128]  = (float(*)[128])SB;
    float (*Bs)[128]  = (float(*)[128])(SB + 4096);
    float (*redR)[16] = (float(*)[16])(SB + 8192);
    float (*redC)[16] = (float(*)[16])(SB + 10240);
    __half* mir = (__half*)SB;                  // seg1/2 epilogue only (post-sync)
    int t = threadIdx.x;

    // ---- dedicated schedule block ----
    if (blockIdx.x == 2080) {
        float* sr2 = SB;
        if (t < 64) {
            float mn = INFINITY, mx = -INFINITY;
#pragma unroll 8
            for (int b = 0; b < 128; b++) {
                mn = fminf(mn, dMinP[b * 64 + t]);
                mx = fmaxf(mx, dMaxP[b * 64 + t]);
            }
            float r = mx - mn;
            sr2[t] = r * r;
        }
        __syncthreads();
        if (t == 0) {
            float d2 = 0.f;
            for (int d = 0; d < 64; d++) d2 += sr2[d];
            sr2[64] = sqrtf(d2);
        }
        __syncthreads();
        float diam = sr2[64];
        double start = 2.0 * log((double)diam);
        double stop  = 2.0 * log(0.05);
        double step  = 2.0 * log(0.8);
        double cnt = ceil((stop - start) / step);
        int n_ar = (cnt > 0.0) ? (int)cnt : 0;
        if (n_ar > MAX_ITERS - 2) n_ar = MAX_ITERS - 2;
        if (t == 0) { dEps[0] = diam * diam; dNeps = n_ar + 2; dBarCnt = 0; }
        if (t >= 1 && t < MAX_ITERS) {
            int k = t - 1;
            dEps[t] = (k < n_ar) ? (float)exp(start + (double)k * step) : 0.0025f;
        }
        return;
    }

    int seg, bm, bn;
    if (blockIdx.x < 1024) {
        seg = 0; bm = blockIdx.x >> 5; bn = blockIdx.x & 31;
    } else {
        int idx = blockIdx.x - 1024;
        seg = 1;
        if (idx >= 528) { seg = 2; idx -= 528; }
        bn = (int)((sqrtf(8.f * (float)idx + 1.f) - 1.f) * 0.5f);
        while ((bn + 1) * (bn + 2) / 2 <= idx) bn++;
        while (bn * (bn + 1) / 2 > idx) bn--;
        bm = idx - bn * (bn + 1) / 2;           // bm <= bn
    }

    const float *A, *B, *a2, *b2;
    if (seg == 0)      { A = x; B = y; a2 = dX2; b2 = dY2; }
    else if (seg == 1) { A = x; B = x; a2 = dX2; b2 = dX2; }
    else               { A = y; B = y; a2 = dY2; b2 = dY2; }

    int m0 = bm * 128, n0 = bn * 128;
    int tm = t >> 4, tn = t & 15;

    ull acc2[8][4];
#pragma unroll
    for (int i = 0; i < 8; i++)
#pragma unroll
        for (int j = 0; j < 4; j++) acc2[i][j] = 0ull;

    for (int kc = 0; kc < 2; kc++) {
#pragma unroll
        for (int l = 0; l < 4; l++) {
            int lin = t + l * 256;
            int r  = lin >> 3;
            int kq = (lin & 7) << 2;
            float4 va = *(const float4*)(A + (size_t)(m0 + r) * DIMS + kc * 32 + kq);
            As[kq + 0][r] = va.x; As[kq + 1][r] = va.y;
            As[kq + 2][r] = va.z; As[kq + 3][r] = va.w;
            float4 vb = *(const float4*)(B + (size_t)(n0 + r) * DIMS + kc * 32 + kq);
            Bs[kq + 0][r] = vb.x; Bs[kq + 1][r] = vb.y;
            Bs[kq + 2][r] = vb.z; Bs[kq + 3][r] = vb.w;
        }
        __syncthreads();
#pragma unroll 8
        for (int k = 0; k < 32; k++) {
            float4 aA = *(const float4*)&As[k][tm * 4];
            float4 aB = *(const float4*)&As[k][64 + tm * 4];
            ulonglong2 bA = *(const ulonglong2*)&Bs[k][tn * 4];
            ulonglong2 bB = *(const ulonglong2*)&Bs[k][64 + tn * 4];
            ull ad[8];
            ad[0] = dupf2_(aA.x); ad[1] = dupf2_(aA.y);
            ad[2] = dupf2_(aA.z); ad[3] = dupf2_(aA.w);
            ad[4] = dupf2_(aB.x); ad[5] = dupf2_(aB.y);
            ad[6] = dupf2_(aB.z); ad[7] = dupf2_(aB.w);
#pragma unroll
            for (int i = 0; i < 8; i++) {
                fma2_(acc2[i][0], ad[i], bA.x);
                fma2_(acc2[i][1], ad[i], bA.y);
                fma2_(acc2[i][2], ad[i], bB.x);
                fma2_(acc2[i][3], ad[i], bB.y);
            }
        }
        __syncthreads();
    }

    float b2r[8];
#pragma unroll
    for (int j = 0; j < 4; j++) {
        b2r[j]     = b2[n0 + tn * 4 + j];
        b2r[4 + j] = b2[n0 + 64 + tn * 4 + j];
    }

    if (seg == 0) {
        // ---- xy epilogue: fp32 store + row/col mins ----
        float cmin[8];
#pragma unroll
        for (int j = 0; j < 8; j++) cmin[j] = INFINITY;
#pragma unroll
        for (int i = 0; i < 8; i++) {
            int rl = (i < 4) ? (tm * 4 + i) : (64 + tm * 4 + (i - 4));
            int row = m0 + rl;
            float ha = 0.5f * a2[row];
            float a0, a1, a2v, a3, a4, a5, a6, a7;
            unpack2_(acc2[i][0], a0, a1);
            unpack2_(acc2[i][1], a2v, a3);
            unpack2_(acc2[i][2], a4, a5);
            unpack2_(acc2[i][3], a6, a7);
            float4 v0, v1;
            v0.x = ha + 0.5f * b2r[0] - a0;
            v0.y = ha + 0.5f * b2r[1] - a1;
            v0.z = ha + 0.5f * b2r[2] - a2v;
            v0.w = ha + 0.5f * b2r[3] - a3;
            v1.x = ha + 0.5f * b2r[4] - a4;
            v1.y = ha + 0.5f * b2r[5] - a5;
            v1.z = ha + 0.5f * b2r[6] - a6;
            v1.w = ha + 0.5f * b2r[7] - a7;
            *(float4*)(dCxy + (size_t)row * NPTS + n0 + tn * 4)      = v0;
            *(float4*)(dCxy + (size_t)row * NPTS + n0 + 64 + tn * 4) = v1;
            float rm = fminf(fminf(fminf(v0.x, v0.y), fminf(v0.z, v0.w)),
                             fminf(fminf(v1.x, v1.y), fminf(v1.z, v1.w)));
            redR[rl][tn] = rm;
            cmin[0] = fminf(cmin[0], v0.x); cmin[1] = fminf(cmin[1], v0.y);
            cmin[2] = fminf(cmin[2], v0.z); cmin[3] = fminf(cmin[3], v0.w);
            cmin[4] = fminf(cmin[4], v1.x); cmin[5] = fminf(cmin[5], v1.y);
            cmin[6] = fminf(cmin[6], v1.z); cmin[7] = fminf(cmin[7], v1.w);
        }
#pragma unroll
        for (int j = 0; j < 8; j++) {
            int cl = (j < 4) ? (tn * 4 + j) : (64 + tn * 4 + (j - 4));
            redC[cl][tm] = cmin[j];
        }
        __syncthreads();
        if (t < 128) {
            float r = INFINITY, c = INFINITY;
#pragma unroll
            for (int k = 0; k < 16; k++) { r = fminf(r, redR[t][k]); c = fminf(c, redC[t][k]); }
            atomicMinFloat(&dRmin[0][m0 + t], r);
            atomicMinFloat(&dRmin[1][n0 + t], c);
        }
    } else {
        // ---- xx/yy epilogue: direct fp16 (offset 0) + mirrored tile via smem ----
        __half* Hc = (seg == 1) ? hCxx : hCyy;
        bool diag = (bm == bn);
#pragma unroll
        for (int i = 0; i < 8; i++) {
            int rl = (i < 4) ? (tm * 4 + i) : (64 + tm * 4 + (i - 4));
            int row = m0 + rl;
            float ha = 0.5f * a2[row];
            float a0, a1, a2v, a3, a4, a5, a6, a7;
            unpack2_(acc2[i][0], a0, a1);
            unpack2_(acc2[i][1], a2v, a3);
            unpack2_(acc2[i][2], a4, a5);
            unpack2_(acc2[i][3], a6, a7);
            float v[8];
            v[0] = ha + 0.5f * b2r[0] - a0;
            v[1] = ha + 0.5f * b2r[1] - a1;
            v[2] = ha + 0.5f * b2r[2] - a2v;
            v[3] = ha + 0.5f * b2r[3] - a3;
            v[4] = ha + 0.5f * b2r[4] - a4;
            v[5] = ha + 0.5f * b2r[5] - a5;
            v[6] = ha + 0.5f * b2r[6] - a6;
            v[7] = ha + 0.5f * b2r[7] - a7;
            half2 p0 = __floats2half2_rn(v[0], v[1]);
            half2 p1 = __floats2half2_rn(v[2], v[3]);
            half2 p2 = __floats2half2_rn(v[4], v[5]);
            half2 p3 = __floats2half2_rn(v[6], v[7]);
            uint2 w0, w1;
            w0.x = *(unsigned*)&p0; w0.y = *(unsigned*)&p1;
            w1.x = *(unsigned*)&p2; w1.y = *(unsigned*)&p3;
            *(uint2*)(Hc + (size_t)row * NPTS + n0 + tn * 4)      = w0;
            *(uint2*)(Hc + (size_t)row * NPTS + n0 + 64 + tn * 4) = w1;
            if (!diag) {
#pragma unroll
                for (int j = 0; j < 4; j++) {
                    mir[(tn * 4 + j) * MIRS + rl]      = __float2half_rn(v[j]);
                    mir[(64 + tn * 4 + j) * MIRS + rl] = __float2half_rn(v[4 + j]);
                }
            }
        }
        if (!diag) {
            __syncthreads();
            int orow = t >> 1, off = (t & 1) * 64;
            const uint4* src = (const uint4*)(mir + orow * MIRS + off);
            uint4* dst = (uint4*)(Hc + (size_t)(n0 + orow) * NPTS + m0 + off);
#pragma unroll
            for (int k = 0; k < 8; k++) dst[k] = src[k];
        }
    }
}

// ---------------- 3) conversions: xy straight + yx transpose ----------------
__global__ void __launch_bounds__(256) conv_all_k() {
    int b = blockIdx.x;
    if (b < 8192) {
        size_t idx = (size_t)b * 2048 + threadIdx.x * 8;
        int row = (int)(idx >> 12);
        float rm = dRmin[0][row];
        float4 a = *(const float4*)(dCxy + idx);
        float4 bb = *(const float4*)(dCxy + idx + 4);
        half2 q0 = __floats2half2_rn(a.x - rm, a.y - rm);
        half2 q1 = __floats2half2_rn(a.z - rm, a.w - rm);
        half2 q2 = __floats2half2_rn(bb.x - rm, bb.y - rm);
        half2 q3 = __floats2half2_rn(bb.z - rm, bb.w - rm);
        uint4 o;
        o.x = *(unsigned*)&q0; o.y = *(unsigned*)&q1;
        o.z = *(unsigned*)&q2; o.w = *(unsigned*)&q3;
        *(uint4*)(hCxy + idx) = o;
    } else {
        __shared__ float tile[32][33];
        int idx2 = b - 8192;                     // 0..16383
        int bx = idx2 & 127, by = idx2 >> 7;
        int x0 = bx * 32, y0 = by * 32;
        int tx = threadIdx.x & 31, ty = threadIdx.x >> 5;  // 32 x 8
#pragma unroll
        for (int j = 0; j < 32; j += 8)
            tile[ty + j][tx] = dCxy[(size_t)(y0 + ty + j) * NPTS + x0 + tx];
        __syncthreads();
#pragma unroll
        for (int j = 0; j < 32; j += 8) {
            int orow = x0 + ty + j;
            float rm = dRmin[1][orow];
            hCyx[(size_t)orow * NPTS + y0 + tx] = __float2half_rn(tile[tx][ty + j] - rm);
        }
    }
}

// ---------------- grid barrier (all NB blocks resident by construction) ----------------
__device__ __forceinline__ void grid_barrier() {
    __syncthreads();
    if (threadIdx.x == 0) {
        unsigned gen = dBarGen;
        __threadfence();
        if (atomicAdd(&dBarCnt, 1) == NB - 1) {
            dBarCnt = 0;
            __threadfence();
            dBarGen = gen + 1;
        } else {
            while (dBarGen == gen) __nanosleep(64);
        }
        __threadfence();
    }
    __syncthreads();
}

// ---------------- softmin core (R14 verbatim, proven) ----------------
template <bool HAS_H>
__device__ __forceinline__ void lse_pair(const __half* __restrict__ Mrow0,
                                         const float* __restrict__ Hs,
                                         float negs1,
                                         float& M0o, float& S0o, float& M1o, float& S1o) {
    const unsigned FULL = 0xffffffffu;
    int lane = threadIdx.x & 31;
    const uint4* p0 = (const uint4*)Mrow0 + lane;
    const uint4* p1 = (const uint4*)(Mrow0 + NPTS) + lane;
    float m0 = -INFINITY, s0 = 0.f, m1 = -INFINITY, s1 = 0.f;
    uint4 A0 = __ldg(p0);
    uint4 A1 = __ldg(p1);
    int hIdx = lane * 8;
#pragma unroll 4
    for (int c = 0; c < 16; c++) {
        uint4 a0 = A0, a1 = A1;
        if (c < 15) { p0 += 32; p1 += 32; A0 = __ldg(p0); A1 = __ldg(p1); }
        float h[8];
        if (HAS_H) {
            float4 hA = *(const float4*)&Hs[hIdx];
            float4 hB = *(const float4*)&Hs[hIdx + 4];
            h[0] = hA.x; h[1] = hA.y; h[2] = hA.z; h[3] = hA.w;
            h[4] = hB.x; h[5] = hB.y; h[6] = hB.z; h[7] = hB.w;
        } else {
#pragma unroll
            for (int k = 0; k < 8; k++) h[k] = C0Z;
        }
        hIdx += 256;
        float z0[8], z1[8];
        const half2* q0 = (const half2*)&a0;
        const half2* q1 = (const half2*)&a1;
#pragma unroll
        for (int k = 0; k < 4; k++) {
            float2 f0 = __half22float2(q0[k]);
            float2 f1 = __half22float2(q1[k]);
            z0[2 * k]     = fmaf(f0.x, negs1, h[2 * k]);
            z0[2 * k + 1] = fmaf(f0.y, negs1, h[2 * k + 1]);
            z1[2 * k]     = fmaf(f1.x, negs1, h[2 * k]);
            z1[2 * k + 1] = fmaf(f1.y, negs1, h[2 * k + 1]);
        }
        float c0m = fmaxf(fmaxf(fmaxf(z0[0], z0[1]), fmaxf(z0[2], z0[3])),
                          fmaxf(fmaxf(z0[4], z0[5]), fmaxf(z0[6], z0[7])));
        float c1m = fmaxf(fmaxf(fmaxf(z1[0], z1[1]), fmaxf(z1[2], z1[3])),
                          fmaxf(fmaxf(z1[4], z1[5]), fmaxf(z1[6], z1[7])));
        if (!__all_sync(FULL, (c0m - m0) < -64.f)) {
            if (c0m > m0) { s0 *= ex2f_(m0 - c0m); m0 = c0m; }
            float e0 = ex2f_(z0[0] - m0), e1 = ex2f_(z0[1] - m0);
            float e2 = ex2f_(z0[2] - m0), e3 = ex2f_(z0[3] - m0);
            float e4 = ex2f_(z0[4] - m0), e5 = ex2f_(z0[5] - m0);
            float e6 = ex2f_(z0[6] - m0), e7 = ex2f_(z0[7] - m0);
            s0 += ((e0 + e1) + (e2 + e3)) + ((e4 + e5) + (e6 + e7));
        }
        if (!__all_sync(FULL, (c1m - m1) < -64.f)) {
            if (c1m > m1) { s1 *= ex2f_(m1 - c1m); m1 = c1m; }
            float e0 = ex2f_(z1[0] - m1), e1 = ex2f_(z1[1] - m1);
            float e2 = ex2f_(z1[2] - m1), e3 = ex2f_(z1[3] - m1);
            float e4 = ex2f_(z1[4] - m1), e5 = ex2f_(z1[5] - m1);
            float e6 = ex2f_(z1[6] - m1), e7 = ex2f_(z1[7] - m1);
            s1 += ((e0 + e1) + (e2 + e3)) + ((e4 + e5) + (e6 + e7));
        }
        if ((c & 3) == 3) {
            float w = m0;
#pragma unroll
            for (int o = 16; o; o >>= 1) w = fmaxf(w, __shfl_xor_sync(FULL, w, o));
            if (w > m0) { s0 *= ex2f_(m0 - w); m0 = w; }
            w = m1;
#pragma unroll
            for (int o = 16; o; o >>= 1) w = fmaxf(w, __shfl_xor_sync(FULL, w, o));
            if (w > m1) { s1 *= ex2f_(m1 - w); m1 = w; }
        }
    }
#pragma unroll
    for (int o = 16; o; o >>= 1) {
        s0 += __shfl_xor_sync(FULL, s0, o);
        s1 += __shfl_xor_sync(FULL, s1, o);
    }
    M0o = m0; S0o = s0; M1o = m1; S1o = s1;
}

// ---------------- 4) persistent Sinkhorn (R14 verbatim, proven) ----------------
__global__ void __launch_bounds__(256, 4) sinkhorn_k(float* __restrict__ out) {
    int bid = blockIdx.x;
    int seg = bid >> 7, bb = bid & 127;   // 128 blocks/seg, 32 rows/block
    int t = threadIdx.x, w = t >> 5, lane = t & 31;
    __shared__ __align__(16) float Hs[NPTS];
    const __half* Mbase = seg_M(seg);
    const float* rmin = dRmin[seg];
    int n = dNeps;

    // ---- init pass: eps0, H = log-weights only ----
    {
        float eps = dEps[0];
        float negs1 = -(1.f / eps) * INVLN2f;
        float el2 = eps * LN2f;
#pragma unroll
        for (int rp = 0; rp < 2; rp++) {
            int row0 = bb * 32 + rp * 16 + w * 2;
            float m0, s0, m1, s1;
            lse_pair<false>(Mbase + (size_t)row0 * NPTS, nullptr, negs1, m0, s0, m1, s1);
            if (lane == 0) {
                dF[0][seg][row0]     = rmin[row0]     - el2 * (m0 + lg2f_(s0));
                dF[0][seg][row0 + 1] = rmin[row0 + 1] - el2 * (m1 + lg2f_(s1));
            }
        }
    }
    grid_barrier();

    // ---- annealing loop: exactly n data-dependent iterations ----
    for (int it = 0; it < n; it++) {
        int src = it & 1, dst = src ^ 1;
        float eps = dEps[it];
        float s1f = (1.f / eps) * INVLN2f;
        const float* Hv = dF[src][hslot(seg)];
        for (int i = t * 4; i < NPTS; i += 1024) {
            float4 hv = *(const float4*)&Hv[i];
            float4 o;
            o.x = fmaf(hv.x, s1f, C0Z); o.y = fmaf(hv.y, s1f, C0Z);
            o.z = fmaf(hv.z, s1f, C0Z); o.w = fmaf(hv.w, s1f, C0Z);
            *(float4*)&Hs[i] = o;
        }
        __syncthreads();
        float el2 = eps * LN2f;
#pragma unroll
        for (int rp = 0; rp < 2; rp++) {
            int row0 = bb * 32 + rp * 16 + w * 2;
            float m0, s0, m1, s1;
            lse_pair<true>(Mbase + (size_t)row0 * NPTS, Hs, -s1f, m0, s0, m1, s1);
            if (lane == 0) {
                float ft0 = rmin[row0]     - el2 * (m0 + lg2f_(s0));
                float ft1 = rmin[row0 + 1] - el2 * (m1 + lg2f_(s1));
                dF[dst][seg][row0]     = 0.5f * (dF[src][seg][row0]     + ft0);
                dF[dst][seg][row0 + 1] = 0.5f * (dF[src][seg][row0 + 1] + ft1);
            }
        }
        grid_barrier();
    }

    // ---- final extrapolation at eps = BLUR^P ----
    {
        int src = n & 1;
        float eps = 0.0025f;
        float s1f = (1.f / eps) * INVLN2f;
        const float* Hv = dF[src][hslot(seg)];
        for (int i = t * 4; i < NPTS; i += 1024) {
            float4 hv = *(const float4*)&Hv[i];
            float4 o;
            o.x = fmaf(hv.x, s1f, C0Z); o.y = fmaf(hv.y, s1f, C0Z);
            o.z = fmaf(hv.z, s1f, C0Z); o.w = fmaf(hv.w, s1f, C0Z);
            *(float4*)&Hs[i] = o;
        }
        __syncthreads();
        float el2 = eps * LN2f;
#pragma unroll
        for (int rp = 0; rp < 2; rp++) {
            int row0 = bb * 32 + rp * 16 + w * 2;
            float m0, s0, m1, s1;
            lse_pair<true>(Mbase + (size_t)row0 * NPTS, Hs, -s1f, m0, s0, m1, s1);
            if (lane == 0) {
                dFin[seg][row0]     = rmin[row0]     - el2 * (m0 + lg2f_(s0));
                dFin[seg][row0 + 1] = rmin[row0 + 1] - el2 * (m1 + lg2f_(s1));
            }
        }
    }
    grid_barrier();

    // ---- reduction by block 0 ----
    if (bid == 0) {
        float s = 0.f;
        for (int i = t; i < NPTS; i += 256)
            s += (dFin[0][i] - dFin[2][i]) + (dFin[1][i] - dFin[3][i]);
#pragma unroll
        for (int o = 16; o; o >>= 1) s += __shfl_xor_sync(0xffffffffu, s, o);
        __shared__ float sm[8];
        if (lane == 0) sm[w] = s;
        __syncthreads();
        if (t == 0) {
            float tot = 0.f;
            for (int k = 0; k < 8; k++) tot += sm[k];
            out[0] = tot * (1.0f / NPTS);
        }
    }
}

// ---------------- launch ----------------
extern "C" void kernel_launch(void* const* d_in, const int* in_sizes, int n_in,
                              void* d_out, int out_size) {
    const float* x = (const float*)d_in[0];
    const float* y = (const float*)d_in[1];
    float* out = (float*)d_out;

    prep_k<<<128, 256>>>(x, y);                     // 1
    gemm_cost<<<2081, 256>>>(x, y);                 // 2 (block 2080 = eps schedule)
    conv_all_k<<<8192 + 16384, 256>>>();            // 3
    sinkhorn_k<<<NB, 256>>>(out);                   // 4  <- profiled slot
}

// round 17
// speedup vs baseline: 1.3429x; 1.0197x over previous
#include <cuda_runtime.h>
#include <cuda_fp16.h>
#include <math.h>

#define NPTS 4096
#define DIMS 64
#define MAX_ITERS 44
#define NB 512                       /* persistent grid; occupancy-4 guaranteed */
#define NEGLOGN (-8.317766166719343f)
#define LN2f 0.6931471805599453f
#define INVLN2f 1.4426950408889634f
#define C0Z (NEGLOGN * INVLN2f)

typedef unsigned long long ull;

// ---------------- static device scratch ----------------
__device__ float dCxy[(size_t)NPTS * NPTS];
__device__ __align__(16) __half hCxy[(size_t)NPTS * NPTS];
__device__ __align__(16) __half hCyx[(size_t)NPTS * NPTS];
__device__ __align__(16) __half hCxx[(size_t)NPTS * NPTS];
__device__ __align__(16) __half hCyy[(size_t)NPTS * NPTS];
// [0] Cxy row mins, [1] Cxy col mins (= Cyx row mins), [2]=[3]= 0 (xx/yy offset-free)
__device__ float dRmin[4][NPTS];
__device__ float dX2[NPTS];
__device__ float dY2[NPTS];
__device__ float dMinP[128 * DIMS];
__device__ float dMaxP[128 * DIMS];
__device__ float dEps[MAX_ITERS];
__device__ int   dNeps;
// slots: 0=f_ba, 1=g_ab, 2=f_aa, 3=g_bb
__device__ float dF[2][4][NPTS];
__device__ float dFin[4][NPTS];
__device__ unsigned int dBarCnt;
__device__ volatile unsigned int dBarGen;

// ---------------- helpers ----------------
__device__ __forceinline__ float ex2f_(float x) {
    float r; asm("ex2.approx.ftz.f32 %0, %1;" : "=f"(r) : "f"(x)); return r;
}
__device__ __forceinline__ float lg2f_(float x) {
    float r; asm("lg2.approx.ftz.f32 %0, %1;" : "=f"(r) : "f"(x)); return r;
}
__device__ __forceinline__ void atomicMinFloat(float* addr, float v) {
    int* ai = (int*)addr;
    int old = *ai;
    while (__int_as_float(old) > v) {
        int assumed = old;
        old = atomicCAS(ai, assumed, __float_as_int(v));
        if (old == assumed) break;
    }
}
__device__ __forceinline__ const __half* seg_M(int s) {
    return (s == 0) ? hCxy : (s == 1) ? hCyx : (s == 2) ? hCxx : hCyy;
}
__device__ __forceinline__ int hslot(int s) {
    return (s == 0) ? 1 : (s == 1) ? 0 : s;
}
// f32x2 packed helpers
__device__ __forceinline__ ull dupf2_(float a) {
    ull r; asm("mov.b64 %0, {%1, %1};" : "=l"(r) : "f"(a)); return r;
}
__device__ __forceinline__ void fma2_(ull& d, ull a, ull b) {
    asm("fma.rn.f32x2 %0, %1, %2, %0;" : "+l"(d) : "l"(a), "l"(b));
}
__device__ __forceinline__ void unpack2_(ull p, float& lo, float& hi) {
    asm("mov.b64 {%0, %1}, %2;" : "=f"(lo), "=f"(hi) : "l"(p));
}

// ---------------- 1) prep: init dRmin + minmax partials + row norms ----------------
__global__ void __launch_bounds__(256) prep_k(const float* __restrict__ x,
                                              const float* __restrict__ y) {
    int t = threadIdx.x, b = blockIdx.x;  // 128 blocks x 256 threads
    int gi = b * 256 + t;
    if (gi < 4 * NPTS) ((float*)dRmin)[gi] = (gi < 2 * NPTS) ? INFINITY : 0.f;

    int dim = t & 63, sub = t >> 6;
    float mn = INFINITY, mx = -INFINITY;
    for (int row = b * 4 + sub; row < 2 * NPTS; row += 128 * 4) {
        const float* p = (row < NPTS) ? (x + (size_t)row * DIMS)
                                      : (y + (size_t)(row - NPTS) * DIMS);
        float v = p[dim];
        mn = fminf(mn, v); mx = fmaxf(mx, v);
    }
    __shared__ float smn[256], smx[256];
    smn[t] = mn; smx[t] = mx;
    __syncthreads();
    if (t < 64) {
        mn = fminf(fminf(smn[t], smn[t + 64]), fminf(smn[t + 128], smn[t + 192]));
        mx = fmaxf(fmaxf(smx[t], smx[t + 64]), fmaxf(smx[t + 128], smx[t + 192]));
        dMinP[b * 64 + t] = mn;
        dMaxP[b * 64 + t] = mx;
    }

    int row = b * 64 + (t >> 2), q = t & 3;
    const float* p = (row < NPTS) ? (x + (size_t)row * DIMS)
                                  : (y + (size_t)(row - NPTS) * DIMS);
    float s = 0.f;
#pragma unroll
    for (int k = 0; k < 4; k++) {
        float4 v = ((const float4*)p)[q * 4 + k];
        s += v.x * v.x + v.y * v.y + v.z * v.z + v.w * v.w;
    }
    s += __shfl_xor_sync(0xffffffffu, s, 1);
    s += __shfl_xor_sync(0xffffffffu, s, 2);
    if (q == 0) {
        if (row < NPTS) dX2[row] = s; else dY2[row - NPTS] = s;
    }
}

// ---------------- 2) cost matrices ----------------
// grid: [0,1024) xy full; [1024,1552) xx upper-triangle; [1552,2080) yy upper-triangle;
// 2080 = eps schedule. xx/yy write fp16 directly (offset 0) + mirrored tile (symmetry).
#define MIRS 136   /* mirror smem stride in halves: 16B-aligned rows, 2-way conflicts */
__global__ void __launch_bounds__(256) gemm_cost(const float* __restrict__ x,
                                                 const float* __restrict__ y) {
    __shared__ __align__(16) float SB[12288];   // 48KB, manually partitioned
    float (*As)[128]  = (float(*)[128])SB;
    float (*Bs)[128]  = (float(*)[128])(SB + 4096);
    float (*redR)[16] = (float(*)[16])(SB + 8192);
    float (*redC)[16] = (float(*)[16])(SB + 10240);
    __half* mir = (__half*)SB;                  // seg1/2 epilogue only (post-sync)
    int t = threadIdx.x;

    // ---- dedicated schedule block ----
    if (blockIdx.x == 2080) {
        float* sr2 = SB;
        if (t < 64) {
            float mn = INFINITY, mx = -INFINITY;
#pragma unroll 8
            for (int b = 0; b < 128; b++) {
                mn = fminf(mn, dMinP[b * 64 + t]);
                mx = fmaxf(mx, dMaxP[b * 64 + t]);
            }
            float r = mx - mn;
            sr2[t] = r * r;
        }
        __syncthreads();
        if (t == 0) {
            float d2 = 0.f;
            for (int d = 0; d < 64; d++) d2 += sr2[d];
            sr2[64] = sqrtf(d2);
        }
        __syncthreads();
        float diam = sr2[64];
        double start = 2.0 * log((double)diam);
        double stop  = 2.0 * log(0.05);
        double step  = 2.0 * log(0.8);
        double cnt = ceil((stop - start) / step);
        int n_ar = (cnt > 0.0) ? (int)cnt : 0;
        if (n_ar > MAX_ITERS - 2) n_ar = MAX_ITERS - 2;
        if (t == 0) { dEps[0] = diam * diam; dNeps = n_ar + 2; dBarCnt = 0; }
        if (t >= 1 && t < MAX_ITERS) {
            int k = t - 1;
            dEps[t] = (k < n_ar) ? (float)exp(start + (double)k * step) : 0.0025f;
        }
        return;
    }

    int seg, bm, bn;
    if (blockIdx.x < 1024) {
        seg = 0; bm = blockIdx.x >> 5; bn = blockIdx.x & 31;
    } else {
        int idx = blockIdx.x - 1024;
        seg = 1;
        if (idx >= 528) { seg = 2; idx -= 528; }
        bn = (int)((sqrtf(8.f * (float)idx + 1.f) - 1.f) * 0.5f);
        while ((bn + 1) * (bn + 2) / 2 <= idx) bn++;
        while (bn * (bn + 1) / 2 > idx) bn--;
        bm = idx - bn * (bn + 1) / 2;           // bm <= bn
    }

    const float *A, *B, *a2, *b2;
    if (seg == 0)      { A = x; B = y; a2 = dX2; b2 = dY2; }
    else if (seg == 1) { A = x; B = x; a2 = dX2; b2 = dX2; }
    else               { A = y; B = y; a2 = dY2; b2 = dY2; }

    int m0 = bm * 128, n0 = bn * 128;
    int tm = t >> 4, tn = t & 15;

    ull acc2[8][4];
#pragma unroll
    for (int i = 0; i < 8; i++)
#pragma unroll
        for (int j = 0; j < 4; j++) acc2[i][j] = 0ull;

    for (int kc = 0; kc < 2; kc++) {
#pragma unroll
        for (int l = 0; l < 4; l++) {
            int lin = t + l * 256;
            int r  = lin >> 3;
            int kq = (lin & 7) << 2;
            float4 va = *(const float4*)(A + (size_t)(m0 + r) * DIMS + kc * 32 + kq);
            As[kq + 0][r] = va.x; As[kq + 1][r] = va.y;
            As[kq + 2][r] = va.z; As[kq + 3][r] = va.w;
            float4 vb = *(const float4*)(B + (size_t)(n0 + r) * DIMS + kc * 32 + kq);
            Bs[kq + 0][r] = vb.x; Bs[kq + 1][r] = vb.y;
            Bs[kq + 2][r] = vb.z; Bs[kq + 3][r] = vb.w;
        }
        __syncthreads();
#pragma unroll 8
        for (int k = 0; k < 32; k++) {
            float4 aA = *(const float4*)&As[k][tm * 4];
            float4 aB = *(const float4*)&As[k][64 + tm * 4];
            ulonglong2 bA = *(const ulonglong2*)&Bs[k][tn * 4];
            ulonglong2 bB = *(const ulonglong2*)&Bs[k][64 + tn * 4];
            ull ad[8];
            ad[0] = dupf2_(aA.x); ad[1] = dupf2_(aA.y);
            ad[2] = dupf2_(aA.z); ad[3] = dupf2_(aA.w);
            ad[4] = dupf2_(aB.x); ad[5] = dupf2_(aB.y);
            ad[6] = dupf2_(aB.z); ad[7] = dupf2_(aB.w);
#pragma unroll
            for (int i = 0; i < 8; i++) {
                fma2_(acc2[i][0], ad[i], bA.x);
                fma2_(acc2[i][1], ad[i], bA.y);
                fma2_(acc2[i][2], ad[i], bB.x);
                fma2_(acc2[i][3], ad[i], bB.y);
            }
        }
        __syncthreads();
    }

    float b2r[8];
#pragma unroll
    for (int j = 0; j < 4; j++) {
        b2r[j]     = b2[n0 + tn * 4 + j];
        b2r[4 + j] = b2[n0 + 64 + tn * 4 + j];
    }

    if (seg == 0) {
        // ---- xy epilogue: fp32 store + row/col mins ----
        float cmin[8];
#pragma unroll
        for (int j = 0; j < 8; j++) cmin[j] = INFINITY;
#pragma unroll
        for (int i = 0; i < 8; i++) {
            int rl = (i < 4) ? (tm * 4 + i) : (64 + tm * 4 + (i - 4));
            int row = m0 + rl;
            float ha = 0.5f * a2[row];
            float a0, a1, a2v, a3, a4, a5, a6, a7;
            unpack2_(acc2[i][0], a0, a1);
            unpack2_(acc2[i][1], a2v, a3);
            unpack2_(acc2[i][2], a4, a5);
            unpack2_(acc2[i][3], a6, a7);
            float4 v0, v1;
            v0.x = ha + 0.5f * b2r[0] - a0;
            v0.y = ha + 0.5f * b2r[1] - a1;
            v0.z = ha + 0.5f * b2r[2] - a2v;
            v0.w = ha + 0.5f * b2r[3] - a3;
            v1.x = ha + 0.5f * b2r[4] - a4;
            v1.y = ha + 0.5f * b2r[5] - a5;
            v1.z = ha + 0.5f * b2r[6] - a6;
            v1.w = ha + 0.5f * b2r[7] - a7;
            *(float4*)(dCxy + (size_t)row * NPTS + n0 + tn * 4)      = v0;
            *(float4*)(dCxy + (size_t)row * NPTS + n0 + 64 + tn * 4) = v1;
            float rm = fminf(fminf(fminf(v0.x, v0.y), fminf(v0.z, v0.w)),
                             fminf(fminf(v1.x, v1.y), fminf(v1.z, v1.w)));
            redR[rl][tn] = rm;
            cmin[0] = fminf(cmin[0], v0.x); cmin[1] = fminf(cmin[1], v0.y);
            cmin[2] = fminf(cmin[2], v0.z); cmin[3] = fminf(cmin[3], v0.w);
            cmin[4] = fminf(cmin[4], v1.x); cmin[5] = fminf(cmin[5], v1.y);
            cmin[6] = fminf(cmin[6], v1.z); cmin[7] = fminf(cmin[7], v1.w);
        }
#pragma unroll
        for (int j = 0; j < 8; j++) {
            int cl = (j < 4) ? (tn * 4 + j) : (64 + tn * 4 + (j - 4));
            redC[cl][tm] = cmin[j];
        }
        __syncthreads();
        if (t < 128) {
            float r = INFINITY, c = INFINITY;
#pragma unroll
            for (int k = 0; k < 16; k++) { r = fminf(r, redR[t][k]); c = fminf(c, redC[t][k]); }
            atomicMinFloat(&dRmin[0][m0 + t], r);
            atomicMinFloat(&dRmin[1][n0 + t], c);
        }
    } else {
        // ---- xx/yy epilogue: direct fp16 (offset 0) + mirrored tile via smem ----
        __half* Hc = (seg == 1) ? hCxx : hCyy;
        bool diag = (bm == bn);
#pragma unroll
        for (int i = 0; i < 8; i++) {
            int rl = (i < 4) ? (tm * 4 + i) : (64 + tm * 4 + (i - 4));
            int row = m0 + rl;
            float ha = 0.5f * a2[row];
            float a0, a1, a2v, a3, a4, a5, a6, a7;
            unpack2_(acc2[i][0], a0, a1);
            unpack2_(acc2[i][1], a2v, a3);
            unpack2_(acc2[i][2], a4, a5);
            unpack2_(acc2[i][3], a6, a7);
            float v[8];
            v[0] = ha + 0.5f * b2r[0] - a0;
            v[1] = ha + 0.5f * b2r[1] - a1;
            v[2] = ha + 0.5f * b2r[2] - a2v;
            v[3] = ha + 0.5f * b2r[3] - a3;
            v[4] = ha + 0.5f * b2r[4] - a4;
            v[5] = ha + 0.5f * b2r[5] - a5;
            v[6] = ha + 0.5f * b2r[6] - a6;
            v[7] = ha + 0.5f * b2r[7] - a7;
            half2 p0 = __floats2half2_rn(v[0], v[1]);
            half2 p1 = __floats2half2_rn(v[2], v[3]);
            half2 p2 = __floats2half2_rn(v[4], v[5]);
            half2 p3 = __floats2half2_rn(v[6], v[7]);
            uint2 w0, w1;
            w0.x = *(unsigned*)&p0; w0.y = *(unsigned*)&p1;
            w1.x = *(unsigned*)&p2; w1.y = *(unsigned*)&p3;
            *(uint2*)(Hc + (size_t)row * NPTS + n0 + tn * 4)      = w0;
            *(uint2*)(Hc + (size_t)row * NPTS + n0 + 64 + tn * 4) = w1;
            if (!diag) {
#pragma unroll
                for (int j = 0; j < 4; j++) {
                    mir[(tn * 4 + j) * MIRS + rl]      = __float2half_rn(v[j]);
                    mir[(64 + tn * 4 + j) * MIRS + rl] = __float2half_rn(v[4 + j]);
                }
            }
        }
        if (!diag) {
            __syncthreads();
            int orow = t >> 1, off = (t & 1) * 64;
            const uint4* src = (const uint4*)(mir + orow * MIRS + off);
            uint4* dst = (uint4*)(Hc + (size_t)(n0 + orow) * NPTS + m0 + off);
#pragma unroll
            for (int k = 0; k < 8; k++) dst[k] = src[k];
        }
    }
}

// ---------------- 3) conversions: xy straight + yx transpose ----------------
__global__ void __launch_bounds__(256) conv_all_k() {
    int b = blockIdx.x;
    if (b < 8192) {
        size_t idx = (size_t)b * 2048 + threadIdx.x * 8;
        int row = (int)(idx >> 12);
        float rm = dRmin[0][row];
        float4 a = *(const float4*)(dCxy + idx);
        float4 bb = *(const float4*)(dCxy + idx + 4);
        half2 q0 = __floats2half2_rn(a.x - rm, a.y - rm);
        half2 q1 = __floats2half2_rn(a.z - rm, a.w - rm);
        half2 q2 = __floats2half2_rn(bb.x - rm, bb.y - rm);
        half2 q3 = __floats2half2_rn(bb.z - rm, bb.w - rm);
        uint4 o;
        o.x = *(unsigned*)&q0; o.y = *(unsigned*)&q1;
        o.z = *(unsigned*)&q2; o.w = *(unsigned*)&q3;
        *(uint4*)(hCxy + idx) = o;
    } else {
        __shared__ float tile[32][33];
        int idx2 = b - 8192;                     // 0..16383
        int bx = idx2 & 127, by = idx2 >> 7;
        int x0 = bx * 32, y0 = by * 32;
        int tx = threadIdx.x & 31, ty = threadIdx.x >> 5;  // 32 x 8
#pragma unroll
        for (int j = 0; j < 32; j += 8)
            tile[ty + j][tx] = dCxy[(size_t)(y0 + ty + j) * NPTS + x0 + tx];
        __syncthreads();
#pragma unroll
        for (int j = 0; j < 32; j += 8) {
            int orow = x0 + ty + j;
            float rm = dRmin[1][orow];
            hCyx[(size_t)orow * NPTS + y0 + tx] = __float2half_rn(tile[tx][ty + j] - rm);
        }
    }
}

// ---------------- grid barrier (all NB blocks resident by construction) ----------------
__device__ __forceinline__ void grid_barrier() {
    __syncthreads();
    if (threadIdx.x == 0) {
        unsigned gen = dBarGen;
        __threadfence();
        if (atomicAdd(&dBarCnt, 1) == NB - 1) {
            dBarCnt = 0;
            __threadfence();
            dBarGen = gen + 1;
        } else {
            while (dBarGen == gen) __nanosleep(64);
        }
        __threadfence();
    }
    __syncthreads();
}

// ---------------- softmin core: serpentine chunk order (REV flips per pass) ----------------
template <bool HAS_H, bool REV>
__device__ __forceinline__ void lse_pair(const __half* __restrict__ Mrow0,
                                         const float* __restrict__ Hs,
                                         float negs1,
                                         float& M0o, float& S0o, float& M1o, float& S1o) {
    const unsigned FULL = 0xffffffffu;
    int lane = threadIdx.x & 31;
    const uint4* b0 = (const uint4*)Mrow0 + lane;
    const uint4* b1 = (const uint4*)(Mrow0 + NPTS) + lane;
    float m0 = -INFINITY, s0 = 0.f, m1 = -INFINITY, s1 = 0.f;
    int cur = REV ? 15 : 0;
    uint4 A0 = __ldg(b0 + cur * 32);
    uint4 A1 = __ldg(b1 + cur * 32);
#pragma unroll 4
    for (int c = 0; c < 16; c++) {
        uint4 a0 = A0, a1 = A1;
        int hIdx = cur * 256 + lane * 8;
        if (c < 15) {
            cur = REV ? (cur - 1) : (cur + 1);
            A0 = __ldg(b0 + cur * 32);
            A1 = __ldg(b1 + cur * 32);
        }
        float h[8];
        if (HAS_H) {
            float4 hA = *(const float4*)&Hs[hIdx];
            float4 hB = *(const float4*)&Hs[hIdx + 4];
            h[0] = hA.x; h[1] = hA.y; h[2] = hA.z; h[3] = hA.w;
            h[4] = hB.x; h[5] = hB.y; h[6] = hB.z; h[7] = hB.w;
        } else {
#pragma unroll
            for (int k = 0; k < 8; k++) h[k] = C0Z;
        }
        float z0[8], z1[8];
        const half2* q0 = (const half2*)&a0;
        const half2* q1 = (const half2*)&a1;
#pragma unroll
        for (int k = 0; k < 4; k++) {
            float2 f0 = __half22float2(q0[k]);
            float2 f1 = __half22float2(q1[k]);
            z0[2 * k]     = fmaf(f0.x, negs1, h[2 * k]);
            z0[2 * k + 1] = fmaf(f0.y, negs1, h[2 * k + 1]);
            z1[2 * k]     = fmaf(f1.x, negs1, h[2 * k]);
            z1[2 * k + 1] = fmaf(f1.y, negs1, h[2 * k + 1]);
        }
        float c0m = fmaxf(fmaxf(fmaxf(z0[0], z0[1]), fmaxf(z0[2], z0[3])),
                          fmaxf(fmaxf(z0[4], z0[5]), fmaxf(z0[6], z0[7])));
        float c1m = fmaxf(fmaxf(fmaxf(z1[0], z1[1]), fmaxf(z1[2], z1[3])),
                          fmaxf(fmaxf(z1[4], z1[5]), fmaxf(z1[6], z1[7])));
        if (!__all_sync(FULL, (c0m - m0) < -64.f)) {
            if (c0m > m0) { s0 *= ex2f_(m0 - c0m); m0 = c0m; }
            float e0 = ex2f_(z0[0] - m0), e1 = ex2f_(z0[1] - m0);
            float e2 = ex2f_(z0[2] - m0), e3 = ex2f_(z0[3] - m0);
            float e4 = ex2f_(z0[4] - m0), e5 = ex2f_(z0[5] - m0);
            float e6 = ex2f_(z0[6] - m0), e7 = ex2f_(z0[7] - m0);
            s0 += ((e0 + e1) + (e2 + e3)) + ((e4 + e5) + (e6 + e7));
        }
        if (!__all_sync(FULL, (c1m - m1) < -64.f)) {
            if (c1m > m1) { s1 *= ex2f_(m1 - c1m); m1 = c1m; }
            float e0 = ex2f_(z1[0] - m1), e1 = ex2f_(z1[1] - m1);
            float e2 = ex2f_(z1[2] - m1), e3 = ex2f_(z1[3] - m1);
            float e4 = ex2f_(z1[4] - m1), e5 = ex2f_(z1[5] - m1);
            float e6 = ex2f_(z1[6] - m1), e7 = ex2f_(z1[7] - m1);
            s1 += ((e0 + e1) + (e2 + e3)) + ((e4 + e5) + (e6 + e7));
        }
        if ((c & 3) == 3) {
            float w = m0;
#pragma unroll
            for (int o = 16; o; o >>= 1) w = fmaxf(w, __shfl_xor_sync(FULL, w, o));
            if (w > m0) { s0 *= ex2f_(m0 - w); m0 = w; }
            w = m1;
#pragma unroll
            for (int o = 16; o; o >>= 1) w = fmaxf(w, __shfl_xor_sync(FULL, w, o));
            if (w > m1) { s1 *= ex2f_(m1 - w); m1 = w; }
        }
    }
#pragma unroll
    for (int o = 16; o; o >>= 1) {
        s0 += __shfl_xor_sync(FULL, s0, o);
        s1 += __shfl_xor_sync(FULL, s1, o);
    }
    M0o = m0; S0o = s0; M1o = m1; S1o = s1;
}

// ---------------- 4) persistent Sinkhorn (serpentine passes) ----------------
__global__ void __launch_bounds__(256, 4) sinkhorn_k(float* __restrict__ out) {
    int bid = blockIdx.x;
    int seg = bid >> 7, bb = bid & 127;   // 128 blocks/seg, 32 rows/block
    int t = threadIdx.x, w = t >> 5, lane = t & 31;
    __shared__ __align__(16) float Hs[NPTS];
    const __half* Mbase = seg_M(seg);
    const float* rmin = dRmin[seg];
    int n = dNeps;

    // ---- init pass (pass 0): eps0, H = log-weights only, forward ----
    {
        float eps = dEps[0];
        float negs1 = -(1.f / eps) * INVLN2f;
        float el2 = eps * LN2f;
#pragma unroll
        for (int rp = 0; rp < 2; rp++) {
            int row0 = bb * 32 + rp * 16 + w * 2;
            float m0, s0, m1, s1;
            lse_pair<false, false>(Mbase + (size_t)row0 * NPTS, nullptr, negs1, m0, s0, m1, s1);
            if (lane == 0) {
                dF[0][seg][row0]     = rmin[row0]     - el2 * (m0 + lg2f_(s0));
                dF[0][seg][row0 + 1] = rmin[row0 + 1] - el2 * (m1 + lg2f_(s1));
            }
        }
    }
    grid_barrier();

    // ---- annealing loop: pass it+1 direction = (it+1)&1 ----
    for (int it = 0; it < n; it++) {
        int src = it & 1, dst = src ^ 1;
        float eps = dEps[it];
        float s1f = (1.f / eps) * INVLN2f;
        const float* Hv = dF[src][hslot(seg)];
        for (int i = t * 4; i < NPTS; i += 1024) {
            float4 hv = *(const float4*)&Hv[i];
            float4 o;
            o.x = fmaf(hv.x, s1f, C0Z); o.y = fmaf(hv.y, s1f, C0Z);
            o.z = fmaf(hv.z, s1f, C0Z); o.w = fmaf(hv.w, s1f, C0Z);
            *(float4*)&Hs[i] = o;
        }
        __syncthreads();
        float el2 = eps * LN2f;
        bool rev = ((it + 1) & 1) != 0;
#pragma unroll
        for (int rp = 0; rp < 2; rp++) {
            int row0 = bb * 32 + rp * 16 + w * 2;
            float m0, s0, m1, s1;
            if (rev)
                lse_pair<true, true >(Mbase + (size_t)row0 * NPTS, Hs, -s1f, m0, s0, m1, s1);
            else
                lse_pair<true, false>(Mbase + (size_t)row0 * NPTS, Hs, -s1f, m0, s0, m1, s1);
            if (lane == 0) {
                float ft0 = rmin[row0]     - el2 * (m0 + lg2f_(s0));
                float ft1 = rmin[row0 + 1] - el2 * (m1 + lg2f_(s1));
                dF[dst][seg][row0]     = 0.5f * (dF[src][seg][row0]     + ft0);
                dF[dst][seg][row0 + 1] = 0.5f * (dF[src][seg][row0 + 1] + ft1);
            }
        }
        grid_barrier();
    }

    // ---- final extrapolation at eps = BLUR^P, direction = (n+1)&1 ----
    {
        int src = n & 1;
        float eps = 0.0025f;
        float s1f = (1.f / eps) * INVLN2f;
        const float* Hv = dF[src][hslot(seg)];
        for (int i = t * 4; i < NPTS; i += 1024) {
            float4 hv = *(const float4*)&Hv[i];
            float4 o;
            o.x = fmaf(hv.x, s1f, C0Z); o.y = fmaf(hv.y, s1f, C0Z);
            o.z = fmaf(hv.z, s1f, C0Z); o.w = fmaf(hv.w, s1f, C0Z);
            *(float4*)&Hs[i] = o;
        }
        __syncthreads();
        float el2 = eps * LN2f;
        bool rev = ((n + 1) & 1) != 0;
#pragma unroll
        for (int rp = 0; rp < 2; rp++) {
            int row0 = bb * 32 + rp * 16 + w * 2;
            float m0, s0, m1, s1;
            if (rev)
                lse_pair<true, true >(Mbase + (size_t)row0 * NPTS, Hs, -s1f, m0, s0, m1, s1);
            else
                lse_pair<true, false>(Mbase + (size_t)row0 * NPTS, Hs, -s1f, m0, s0, m1, s1);
            if (lane == 0) {
                dFin[seg][row0]     = rmin[row0]     - el2 * (m0 + lg2f_(s0));
                dFin[seg][row0 + 1] = rmin[row0 + 1] - el2 * (m1 + lg2f_(s1));
            }
        }
    }
    grid_barrier();

    // ---- reduction by block 0 ----
    if (bid == 0) {
        float s = 0.f;
        for (int i = t; i < NPTS; i += 256)
            s += (dFin[0][i] - dFin[2][i]) + (dFin[1][i] - dFin[3][i]);
#pragma unroll
        for (int o = 16; o; o >>= 1) s += __shfl_xor_sync(0xffffffffu, s, o);
        __shared__ float sm[8];
        if (lane == 0) sm[w] = s;
        __syncthreads();
        if (t == 0) {
            float tot = 0.f;
            for (int k = 0; k < 8; k++) tot += sm[k];
            out[0] = tot * (1.0f / NPTS);
        }
    }
}

// ---------------- launch ----------------
extern "C" void kernel_launch(void* const* d_in, const int* in_sizes, int n_in,
                              void* d_out, int out_size) {
    const float* x = (const float*)d_in[0];
    const float* y = (const float*)d_in[1];
    float* out = (float*)d_out;

    prep_k<<<128, 256>>>(x, y);                     // 1
    gemm_cost<<<2081, 256>>>(x, y);                 // 2 (block 2080 = eps schedule)
    conv_all_k<<<8192 + 16384, 256>>>();            // 3
    sinkhorn_k<<<NB, 256>>>(out);                   // 4  <- profiled slot
}